// round 12
// baseline (speedup 1.0000x reference)
#include <cuda_runtime.h>
#include <cuda_fp16.h>
#include <math.h>
#include <stdint.h>

#define Dm 2048
#define Hn 16
#define Dh 128
#define Bb 2
#define Ll 2048
#define Mm (Bb*Ll)   /* 4096 rows */
#define SCALE_C 0.08838834764831845f   /* 1/sqrt(128) */

// ---------------- scratch (static device globals; no runtime allocation) ----
__device__ __half g_ahi[(size_t)Mm * Dm];   // x split hi, later O split hi
__device__ __half g_alo[(size_t)Mm * Dm];
__device__ __half g_w[(size_t)4 * Dm * Dm]; // Wq,Wk,Wv,Wo single fp16
__device__ __half g_qhi[(size_t)Mm * Dm];
__device__ __half g_qlo[(size_t)Mm * Dm];
__device__ __half g_k[(size_t)Mm * Dm];     // K single fp16 (post-rope)
__device__ __half g_v[(size_t)Mm * Dm];     // V single fp16
__device__ float g_invf[Dh/2];

// ======================= helpers =============================================
__device__ __forceinline__ uint32_t smem_u32(const void* p) {
    uint32_t a;
    asm("{ .reg .u64 t; cvta.to.shared.u64 t, %1; cvt.u32.u64 %0, t; }"
        : "=r"(a) : "l"(p));
    return a;
}
__device__ __forceinline__ void cp_async16(uint32_t saddr, const void* gaddr) {
    asm volatile("cp.async.cg.shared.global [%0], [%1], 16;"
                 :: "r"(saddr), "l"(gaddr) : "memory");
}
#define CP_COMMIT() asm volatile("cp.async.commit_group;" ::: "memory")
#define CP_WAIT1()  asm volatile("cp.async.wait_group 1;" ::: "memory")
#define CP_WAIT0()  asm volatile("cp.async.wait_group 0;" ::: "memory")

__device__ __forceinline__ void ldsm4(uint32_t* d, uint32_t a) {
    asm volatile("ldmatrix.sync.aligned.m8n8.x4.shared.b16 {%0,%1,%2,%3}, [%4];"
                 : "=r"(d[0]), "=r"(d[1]), "=r"(d[2]), "=r"(d[3]) : "r"(a));
}
__device__ __forceinline__ void ldsm4t(uint32_t* d, uint32_t a) {
    asm volatile("ldmatrix.sync.aligned.m8n8.x4.trans.shared.b16 {%0,%1,%2,%3}, [%4];"
                 : "=r"(d[0]), "=r"(d[1]), "=r"(d[2]), "=r"(d[3]) : "r"(a));
}
__device__ __forceinline__ void mma16816(float* d, const uint32_t* a,
                                         uint32_t b0, uint32_t b1) {
    asm volatile(
        "mma.sync.aligned.m16n8k16.row.col.f32.f16.f16.f32 "
        "{%0,%1,%2,%3}, {%4,%5,%6,%7}, {%8,%9}, {%0,%1,%2,%3};"
        : "+f"(d[0]), "+f"(d[1]), "+f"(d[2]), "+f"(d[3])
        : "r"(a[0]), "r"(a[1]), "r"(a[2]), "r"(a[3]), "r"(b0), "r"(b1));
}
__device__ __forceinline__ uint32_t pack_hi2h(float a, float b) {
    __half2 t = __floats2half2_rn(a, b);
    return *reinterpret_cast<uint32_t*>(&t);
}
__device__ __forceinline__ uint32_t pack_lo2h(float a, float b) {
    float ra = a - __half2float(__float2half_rn(a));
    float rb = b - __half2float(__float2half_rn(b));
    __half2 t = __floats2half2_rn(ra, rb);
    return *reinterpret_cast<uint32_t*>(&t);
}

// ---------------- inv_freq table --------------------------------------------
__global__ void invf_kernel() {
    int i = threadIdx.x;
    if (i < Dh/2)
        g_invf[i] = (float)pow(10000.0, -(double)(2*i) / (double)Dh);
}

// ---------------- fp32 -> fp16 hi/lo split (x) --------------------------------
__global__ void split_x(const float4* __restrict__ src,
                        __half2* __restrict__ hi, __half2* __restrict__ lo, int n4)
{
    int i = blockIdx.x * blockDim.x + threadIdx.x;
    if (i >= n4) return;
    float4 v = src[i];
    uint32_t h0 = pack_hi2h(v.x, v.y), h1 = pack_hi2h(v.z, v.w);
    uint32_t l0 = pack_lo2h(v.x, v.y), l1 = pack_lo2h(v.z, v.w);
    hi[2*i]   = *reinterpret_cast<__half2*>(&h0);
    hi[2*i+1] = *reinterpret_cast<__half2*>(&h1);
    lo[2*i]   = *reinterpret_cast<__half2*>(&l0);
    lo[2*i+1] = *reinterpret_cast<__half2*>(&l1);
}

// ---------------- all 4 weights -> packed single fp16 ------------------------
__global__ void split4_w(const float4* __restrict__ w0, const float4* __restrict__ w1,
                         const float4* __restrict__ w2, const float4* __restrict__ w3,
                         __half2* __restrict__ w)
{
    const int n4each = (Dm * Dm) / 4;     // 2^20
    int idx = blockIdx.x * blockDim.x + threadIdx.x;
    int t = idx >> 20;
    int r = idx & (n4each - 1);
    const float4* s = (t == 0) ? w0 : (t == 1) ? w1 : (t == 2) ? w2 : w3;
    float4 v = s[r];
    w[2*(size_t)idx]   = __floats2half2_rn(v.x, v.y);
    w[2*(size_t)idx+1] = __floats2half2_rn(v.z, v.w);
}

// ==== GEMM mainloop: CTA 128x64, 256 thr, 8 warps (4x2 of 32x32), 2 stages ====
// per stage: Ahi(16K) + Alo(16K) + W(8K) = 40KB; 2 stages -> 83KB, 2 CTAs/SM
// Pipeline: wait0 -> bar -> issue(c+1) -> compute(c). ONE barrier per chunk.
#define KC 64
#define TILE_A 16384
#define TILE_W 8192
#define STAGE_B (2*TILE_A + TILE_W)
#define GEMM_SMEM (1024 + 2*STAGE_B)

#define ISSUE_CHUNK(cc) do {                                                   \
    uint32_t sbase = su + ((cc) & 1) * STAGE_B;                                \
    const size_t kb = (size_t)(cc) * (KC * 2);                                 \
    _Pragma("unroll")                                                          \
    for (int t = 0; t < 2; t++) {                                              \
        const char* g = srcs[t] + kb;                                          \
        uint32_t s = sbase + t * TILE_A;                                       \
        _Pragma("unroll")                                                      \
        for (int i = 0; i < 4; i++) {                                          \
            int u = tid + (i << 8);                                            \
            int r = u >> 3;                                                    \
            int cb = (u & 7) << 4;                                             \
            uint32_t off = ((r >> 3) << 10) + ((r & 7) << 7) + (cb ^ ((r & 7) << 4)); \
            cp_async16(s + off, g + (size_t)r * rstride + cb);                 \
        }                                                                      \
    }                                                                          \
    {                                                                          \
        const char* g = srcs[2] + kb;                                          \
        uint32_t s = sbase + 2 * TILE_A;                                       \
        _Pragma("unroll")                                                      \
        for (int i = 0; i < 2; i++) {                                          \
            int u = tid + (i << 8);                                            \
            int r = u >> 3;                                                    \
            int cb = (u & 7) << 4;                                             \
            uint32_t off = ((r >> 3) << 10) + ((r & 7) << 7) + (cb ^ ((r & 7) << 4)); \
            cp_async16(s + off, g + (size_t)r * rstride + cb);                 \
        }                                                                      \
    }                                                                          \
    CP_COMMIT();                                                               \
} while (0)

#define GEMM_MAINLOOP()                                                        \
    uint32_t aoff[2], ar7[2];                                                  \
    _Pragma("unroll")                                                          \
    for (int m = 0; m < 2; m++) {                                              \
        int r = wm*32 + m*16 + (lane & 15);                                    \
        aoff[m] = ((r >> 3) << 10) + ((r & 7) << 7);                           \
        ar7[m]  = r & 7;                                                       \
    }                                                                          \
    uint32_t boff[4], br7[4];                                                  \
    _Pragma("unroll")                                                          \
    for (int n = 0; n < 4; n++) {                                              \
        int r = wn*32 + n*8 + (lane & 7);                                      \
        boff[n] = ((r >> 3) << 10) + ((r & 7) << 7);                           \
        br7[n]  = r & 7;                                                       \
    }                                                                          \
    const uint32_t uA_lo = lane >> 4;                                          \
    const uint32_t uB_lo = lane >> 3;                                          \
    float acc[2][4][4];                                                        \
    _Pragma("unroll")                                                          \
    for (int m = 0; m < 2; m++)                                                \
        _Pragma("unroll")                                                      \
        for (int n = 0; n < 4; n++)                                            \
            _Pragma("unroll")                                                  \
            for (int q = 0; q < 4; q++) acc[m][n][q] = 0.f;                    \
    const int NCH = Ko / KC;                                                   \
    ISSUE_CHUNK(0);                                                            \
    for (int c = 0; c < NCH; c++) {                                            \
        CP_WAIT0();                                                            \
        __syncthreads();                                                       \
        if (c + 1 < NCH) ISSUE_CHUNK(c + 1);                                   \
        const uint32_t st  = su + (c & 1) * STAGE_B;                           \
        const uint32_t SAh = st;                                               \
        const uint32_t SAl = st + TILE_A;                                      \
        const uint32_t SB  = st + 2 * TILE_A;                                  \
        uint32_t bb[2][4][4];                                                  \
        _Pragma("unroll")                                                      \
        for (int kp = 0; kp < 2; kp++)                                         \
            _Pragma("unroll")                                                  \
            for (int n = 0; n < 4; n++) {                                      \
                uint32_t uB = 4*kp + uB_lo;                                    \
                ldsm4(bb[kp][n], SB + boff[n] + ((uB ^ br7[n]) << 4));         \
            }                                                                  \
        _Pragma("unroll")                                                      \
        for (int kp = 0; kp < 2; kp++) {                                       \
            _Pragma("unroll")                                                  \
            for (int ki = 0; ki < 2; ki++) {                                   \
                uint32_t uA = 2*(2*kp + ki) + uA_lo;                           \
                uint32_t ah[2][4], al[2][4];                                   \
                _Pragma("unroll")                                              \
                for (int m = 0; m < 2; m++) {                                  \
                    ldsm4(ah[m], SAh + aoff[m] + ((uA ^ ar7[m]) << 4));        \
                    ldsm4(al[m], SAl + aoff[m] + ((uA ^ ar7[m]) << 4));        \
                }                                                              \
                _Pragma("unroll")                                              \
                for (int m = 0; m < 2; m++)                                    \
                    _Pragma("unroll")                                          \
                    for (int n = 0; n < 4; n++) {                              \
                        mma16816(acc[m][n], ah[m], bb[kp][n][2*ki], bb[kp][n][2*ki+1]); \
                        mma16816(acc[m][n], al[m], bb[kp][n][2*ki], bb[kp][n][2*ki+1]); \
                    }                                                          \
            }                                                                  \
        }                                                                      \
    }

// ---------------- fused QKV GEMM + RoPE + fp16 split epilogue ----------------
// grid (32, 32, 3): z=0 Q (rope+scale, hi/lo), z=1 K (rope), z=2 V
__global__ void __launch_bounds__(256, 2)
gemm_qkv(const __half* __restrict__ Ahi, const __half* __restrict__ Alo,
         const __half* __restrict__ W_all, const int* __restrict__ pos,
         __half* __restrict__ Qh, __half* __restrict__ Ql,
         __half* __restrict__ Kd, __half* __restrict__ Vd)
{
    extern __shared__ char smraw[];
    char* smal = (char*)(((uintptr_t)smraw + 1023) & ~(uintptr_t)1023);
    const uint32_t su = smem_u32(smal);

    const int tid = threadIdx.x;
    const int lane = tid & 31, wid = tid >> 5;
    const int row0 = blockIdx.y << 7;       // 128 rows per CTA
    const int col0 = blockIdx.x << 6;       // 64 cols per CTA
    const int z = blockIdx.z;
    const int wm = wid >> 1, wn = wid & 1;  // 4x2 warp grid, warp tile 32x32
    const int Ko = Dm;

    const char* srcs[3];
    srcs[0] = (const char*)(Ahi + (size_t)row0 * Ko);
    srcs[1] = (const char*)(Alo + (size_t)row0 * Ko);
    srcs[2] = (const char*)(W_all + (size_t)z * Dm * Dm + (size_t)col0 * Ko);
    const size_t rstride = (size_t)Ko * 2;

    GEMM_MAINLOOP();

    if (z == 2) {
#pragma unroll
        for (int m = 0; m < 2; m++) {
            int rw = row0 + wm*32 + m*16 + (lane >> 2);
#pragma unroll
            for (int n = 0; n < 4; n++) {
                int cw = col0 + wn*32 + n*8 + ((lane & 3) << 1);
                *(uint32_t*)(Vd + (size_t)rw * Dm + cw)     = pack_hi2h(acc[m][n][0], acc[m][n][1]);
                *(uint32_t*)(Vd + (size_t)(rw+8) * Dm + cw) = pack_hi2h(acc[m][n][2], acc[m][n][3]);
            }
        }
    } else if (z == 1) {
#pragma unroll
        for (int m = 0; m < 2; m++) {
            int rw = row0 + wm*32 + m*16 + (lane >> 2);
            float p0 = (float)pos[rw];
            float p1 = (float)pos[rw + 8];
#pragma unroll
            for (int n = 0; n < 4; n++) {
                int cw = col0 + wn*32 + n*8 + ((lane & 3) << 1);
                float inv = g_invf[(cw & 127) >> 1];
                float s0, c0, s1, c1;
                sincosf(p0 * inv, &s0, &c0);
                sincosf(p1 * inv, &s1, &c1);
                float e = acc[m][n][0], o = acc[m][n][1];
                *(uint32_t*)(Kd + (size_t)rw * Dm + cw) = pack_hi2h(e*c0 - o*s0, e*s0 + o*c0);
                e = acc[m][n][2]; o = acc[m][n][3];
                *(uint32_t*)(Kd + (size_t)(rw+8) * Dm + cw) = pack_hi2h(e*c1 - o*s1, e*s1 + o*c1);
            }
        }
    } else {
#pragma unroll
        for (int m = 0; m < 2; m++) {
            int rw = row0 + wm*32 + m*16 + (lane >> 2);
            float p0 = (float)pos[rw];
            float p1 = (float)pos[rw + 8];
#pragma unroll
            for (int n = 0; n < 4; n++) {
                int cw = col0 + wn*32 + n*8 + ((lane & 3) << 1);
                float inv = g_invf[(cw & 127) >> 1];
                float s0, c0, s1, c1;
                sincosf(p0 * inv, &s0, &c0);
                sincosf(p1 * inv, &s1, &c1);
                float e = acc[m][n][0], o = acc[m][n][1];
                float re = (e*c0 - o*s0) * SCALE_C, ro = (e*s0 + o*c0) * SCALE_C;
                *(uint32_t*)(Qh + (size_t)rw * Dm + cw) = pack_hi2h(re, ro);
                *(uint32_t*)(Ql + (size_t)rw * Dm + cw) = pack_lo2h(re, ro);
                e = acc[m][n][2]; o = acc[m][n][3];
                re = (e*c1 - o*s1) * SCALE_C; ro = (e*s1 + o*c1) * SCALE_C;
                *(uint32_t*)(Qh + (size_t)(rw+8) * Dm + cw) = pack_hi2h(re, ro);
                *(uint32_t*)(Ql + (size_t)(rw+8) * Dm + cw) = pack_lo2h(re, ro);
            }
        }
    }
}

// ---------------- fp16x2 GEMM (fp32 out) for the Wo projection ---------------
__global__ void __launch_bounds__(256, 2)
gemm_out(const __half* __restrict__ Ahi, const __half* __restrict__ Alo,
         const __half* __restrict__ Bw, float* __restrict__ C, int Ko, int No)
{
    extern __shared__ char smraw[];
    char* smal = (char*)(((uintptr_t)smraw + 1023) & ~(uintptr_t)1023);
    const uint32_t su = smem_u32(smal);

    const int tid = threadIdx.x;
    const int lane = tid & 31, wid = tid >> 5;
    const int row0 = blockIdx.y << 7;
    const int col0 = blockIdx.x << 6;
    const int wm = wid >> 1, wn = wid & 1;

    const char* srcs[3];
    srcs[0] = (const char*)(Ahi + (size_t)row0 * Ko);
    srcs[1] = (const char*)(Alo + (size_t)row0 * Ko);
    srcs[2] = (const char*)(Bw + (size_t)col0 * Ko);
    const size_t rstride = (size_t)Ko * 2;

    GEMM_MAINLOOP();

#pragma unroll
    for (int m = 0; m < 2; m++) {
        int rw = row0 + wm*32 + m*16 + (lane >> 2);
#pragma unroll
        for (int n = 0; n < 4; n++) {
            int cw = col0 + wn*32 + n*8 + ((lane & 3) << 1);
            *(float2*)(C + (size_t)rw * No + cw) =
                make_float2(acc[m][n][0], acc[m][n][1]);
            *(float2*)(C + (size_t)(rw + 8) * No + cw) =
                make_float2(acc[m][n][2], acc[m][n][3]);
        }
    }
}

// ---------------- tensor-core causal flash attention (fp16x2) ----------------
// SMEM: Qhi,Qlo (32KB) + K/V double-buffered (2 x 32KB) = 96KB, occ 2
#define ATT_SMEM 98304

#define ATT_ISSUE(kt) do {                                                     \
    const int kj0 = (kt) << 6;                                                 \
    uint32_t sb = su + 32768 + ((kt) & 1) * 32768;                             \
    _Pragma("unroll")                                                          \
    for (int i = 0; i < 8; i++) {                                              \
        int u = tid + (i << 7);                                                \
        int r = u >> 4, cu = u & 15;                                           \
        uint32_t so = r * 256 + ((cu ^ (r & 7)) << 4);                         \
        size_t go = (rowbase + kj0 + r) * Dm + hoff + cu * 8;                  \
        cp_async16(sb + so, K_g + go);                                         \
        cp_async16(sb + 16384 + so, V_g + go);                                 \
    }                                                                          \
    CP_COMMIT();                                                               \
} while (0)

__global__ void __launch_bounds__(128, 2)
attn_mma(const __half* __restrict__ Qh_g, const __half* __restrict__ Ql_g,
         const __half* __restrict__ K_g, const __half* __restrict__ V_g,
         __half* __restrict__ Ohi, __half* __restrict__ Olo)
{
    extern __shared__ char sm[];
    const uint32_t su = smem_u32(sm);
    const uint32_t QH = 0, QL = 16384;

    const int tid = threadIdx.x, lane = tid & 31, wq = tid >> 5;
    const int qt = (int)(gridDim.x - 1 - blockIdx.x);
    const int h = blockIdx.y, b = blockIdx.z;
    const int qi0 = qt << 6;
    const size_t rowbase = (size_t)b * Ll;
    const int hoff = h * Dh;

    ATT_ISSUE(0);

#pragma unroll
    for (int i = 0; i < 8; i++) {
        int idx = tid + (i << 7);
        int r = idx >> 4, u = idx & 15;
        uint32_t so = r * 256 + ((u ^ (r & 7)) << 4);
        size_t go = (rowbase + qi0 + r) * Dm + hoff + u * 8;
        *(float4*)(sm + QH + so) = *(const float4*)(Qh_g + go);
        *(float4*)(sm + QL + so) = *(const float4*)(Ql_g + go);
    }

    float oacc[16][4];
#pragma unroll
    for (int t = 0; t < 16; t++)
#pragma unroll
        for (int q = 0; q < 4; q++) oacc[t][q] = 0.f;
    float m0 = -1e30f, m1 = -1e30f, l0 = 0.f, l1 = 0.f;

    for (int kt = 0; kt <= qt; kt++) {
        if (kt < qt) { ATT_ISSUE(kt + 1); CP_WAIT1(); }
        else { CP_WAIT0(); }
        __syncthreads();
        const uint32_t KS = su + 32768 + (kt & 1) * 32768;
        const uint32_t VS = KS + 16384;

        // ---- S = Q K^T (fp16x2: Qhi*K + Qlo*K)
        float sacc[8][4];
#pragma unroll
        for (int n = 0; n < 8; n++)
#pragma unroll
            for (int q = 0; q < 4; q++) sacc[n][q] = 0.f;

#pragma unroll
        for (int kg = 0; kg < 4; kg++) {
            uint32_t bk[8][4];
#pragma unroll
            for (int n = 0; n < 8; n++) {
                int r = (n << 3) + (lane & 7);
                int u = (kg << 2) + (lane >> 3);
                ldsm4(bk[n], KS + r * 256 + ((u ^ (r & 7)) << 4));
            }
#pragma unroll
            for (int ki = 0; ki < 2; ki++) {
                int r = (wq << 4) + (lane & 15);
                int u = ((2 * kg + ki) << 1) + (lane >> 4);
                uint32_t o = r * 256 + ((u ^ (r & 7)) << 4);
                uint32_t ah[4], al[4];
                ldsm4(ah, su + QH + o);
                ldsm4(al, su + QL + o);
#pragma unroll
                for (int n = 0; n < 8; n++) {
                    mma16816(sacc[n], ah, bk[n][2*ki], bk[n][2*ki+1]);
                    mma16816(sacc[n], al, bk[n][2*ki], bk[n][2*ki+1]);
                }
            }
        }

        if (kt == qt) {
            int r0 = (wq << 4) + (lane >> 2), r1 = r0 + 8;
            int cb = 2 * (lane & 3);
#pragma unroll
            for (int n = 0; n < 8; n++) {
                int c0 = (n << 3) + cb, c1 = c0 + 1;
                if (c0 > r0) sacc[n][0] = -1e30f;
                if (c1 > r0) sacc[n][1] = -1e30f;
                if (c0 > r1) sacc[n][2] = -1e30f;
                if (c1 > r1) sacc[n][3] = -1e30f;
            }
        }

        float mx0 = -1e30f, mx1 = -1e30f;
#pragma unroll
        for (int n = 0; n < 8; n++) {
            mx0 = fmaxf(mx0, fmaxf(sacc[n][0], sacc[n][1]));
            mx1 = fmaxf(mx1, fmaxf(sacc[n][2], sacc[n][3]));
        }
        mx0 = fmaxf(mx0, __shfl_xor_sync(0xffffffffu, mx0, 1));
        mx0 = fmaxf(mx0, __shfl_xor_sync(0xffffffffu, mx0, 2));
        mx1 = fmaxf(mx1, __shfl_xor_sync(0xffffffffu, mx1, 1));
        mx1 = fmaxf(mx1, __shfl_xor_sync(0xffffffffu, mx1, 2));
        float mn0 = fmaxf(m0, mx0), mn1 = fmaxf(m1, mx1);
        float al0 = __expf(m0 - mn0), al1 = __expf(m1 - mn1);
        float s0 = 0.f, s1 = 0.f;
#pragma unroll
        for (int n = 0; n < 8; n++) {
            sacc[n][0] = __expf(sacc[n][0] - mn0);
            sacc[n][1] = __expf(sacc[n][1] - mn0);
            sacc[n][2] = __expf(sacc[n][2] - mn1);
            sacc[n][3] = __expf(sacc[n][3] - mn1);
            s0 += sacc[n][0] + sacc[n][1];
            s1 += sacc[n][2] + sacc[n][3];
        }
        s0 += __shfl_xor_sync(0xffffffffu, s0, 1);
        s0 += __shfl_xor_sync(0xffffffffu, s0, 2);
        s1 += __shfl_xor_sync(0xffffffffu, s1, 1);
        s1 += __shfl_xor_sync(0xffffffffu, s1, 2);
        l0 = l0 * al0 + s0; l1 = l1 * al1 + s1;
        m0 = mn0; m1 = mn1;
#pragma unroll
        for (int t = 0; t < 16; t++) {
            oacc[t][0] *= al0; oacc[t][1] *= al0;
            oacc[t][2] *= al1; oacc[t][3] *= al1;
        }

        // ---- O += P V
#pragma unroll
        for (int ks = 0; ks < 4; ks++) {
            uint32_t ph[4], pl[4];
            ph[0] = pack_hi2h(sacc[2*ks][0],   sacc[2*ks][1]);
            ph[1] = pack_hi2h(sacc[2*ks][2],   sacc[2*ks][3]);
            ph[2] = pack_hi2h(sacc[2*ks+1][0], sacc[2*ks+1][1]);
            ph[3] = pack_hi2h(sacc[2*ks+1][2], sacc[2*ks+1][3]);
            pl[0] = pack_lo2h(sacc[2*ks][0],   sacc[2*ks][1]);
            pl[1] = pack_lo2h(sacc[2*ks][2],   sacc[2*ks][3]);
            pl[2] = pack_lo2h(sacc[2*ks+1][0], sacc[2*ks+1][1]);
            pl[3] = pack_lo2h(sacc[2*ks+1][2], sacc[2*ks+1][3]);
#pragma unroll
            for (int dg = 0; dg < 8; dg++) {
                int r = (ks << 4) + (lane & 15);
                int u = (dg << 1) + (lane >> 4);
                uint32_t bv[4];
                ldsm4t(bv, VS + r * 256 + ((u ^ (r & 7)) << 4));
                mma16816(oacc[2*dg],   ph, bv[0], bv[1]);
                mma16816(oacc[2*dg+1], ph, bv[2], bv[3]);
                mma16816(oacc[2*dg],   pl, bv[0], bv[1]);
                mma16816(oacc[2*dg+1], pl, bv[2], bv[3]);
            }
        }
        __syncthreads();
    }

    float i0 = 1.f / l0, i1 = 1.f / l1;
    size_t grow0 = rowbase + qi0 + (wq << 4) + (lane >> 2);
    size_t grow1 = grow0 + 8;
    int cb = hoff + 2 * (lane & 3);
#pragma unroll
    for (int t = 0; t < 16; t++) {
        int col = cb + (t << 3);
        float a = oacc[t][0] * i0, d = oacc[t][1] * i0;
        *(uint32_t*)(Ohi + grow0 * Dm + col) = pack_hi2h(a, d);
        *(uint32_t*)(Olo + grow0 * Dm + col) = pack_lo2h(a, d);
        float e = oacc[t][2] * i1, f = oacc[t][3] * i1;
        *(uint32_t*)(Ohi + grow1 * Dm + col) = pack_hi2h(e, f);
        *(uint32_t*)(Olo + grow1 * Dm + col) = pack_lo2h(e, f);
    }
}

// ---------------- launch ------------------------------------------------------
extern "C" void kernel_launch(void* const* d_in, const int* in_sizes, int n_in,
                              void* d_out, int out_size)
{
    const float* x  = (const float*)d_in[0];
    const int*  pos = (const int*)d_in[1];
    const float* Wq = (const float*)d_in[2];
    const float* Wk = (const float*)d_in[3];
    const float* Wv = (const float*)d_in[4];
    const float* Wo = (const float*)d_in[5];
    float* out = (float*)d_out;

    __half *ahi, *alo, *w, *qhi, *qlo, *kd, *vd;
    cudaGetSymbolAddress((void**)&ahi, g_ahi);
    cudaGetSymbolAddress((void**)&alo, g_alo);
    cudaGetSymbolAddress((void**)&w,   g_w);
    cudaGetSymbolAddress((void**)&qhi, g_qhi);
    cudaGetSymbolAddress((void**)&qlo, g_qlo);
    cudaGetSymbolAddress((void**)&kd,  g_k);
    cudaGetSymbolAddress((void**)&vd,  g_v);

    invf_kernel<<<1, 64>>>();

    const int nx4 = (Mm * Dm) / 4;
    const int nw4 = (Dm * Dm) / 4;

    cudaFuncSetAttribute(gemm_qkv,
                         cudaFuncAttributeMaxDynamicSharedMemorySize, GEMM_SMEM);
    cudaFuncSetAttribute(gemm_out,
                         cudaFuncAttributeMaxDynamicSharedMemorySize, GEMM_SMEM);
    cudaFuncSetAttribute(attn_mma,
                         cudaFuncAttributeMaxDynamicSharedMemorySize, ATT_SMEM);

    // x -> fp16 hi/lo
    split_x<<<nx4/256, 256>>>((const float4*)x, (__half2*)ahi, (__half2*)alo, nx4);
    // all 4 weights -> packed single fp16
    split4_w<<<(4*nw4)/256, 256>>>((const float4*)Wq, (const float4*)Wk,
                                   (const float4*)Wv, (const float4*)Wo, (__half2*)w);

    // fused QKV GEMM + RoPE + split (one launch, 3072 CTAs, 256 thr, 2 CTA/SM)
    dim3 qkvgrid(Dm/64, Mm/128, 3);
    gemm_qkv<<<qkvgrid, 256, GEMM_SMEM>>>(ahi, alo, w, pos, qhi, qlo, kd, vd);

    // attention -> O hi/lo into g_ahi/g_alo
    dim3 agrid(Ll/64, Hn, Bb);
    attn_mma<<<agrid, 128, ATT_SMEM>>>(qhi, qlo, kd, vd, ahi, alo);

    // out = O Wo^T (fp32)
    dim3 ggrid(Dm/64, Mm/128);
    gemm_out<<<ggrid, 256, GEMM_SMEM>>>(ahi, alo, w + (size_t)3*Dm*Dm, out, Dm, Dm);
}

// round 13
// speedup vs baseline: 1.0987x; 1.0987x over previous
#include <cuda_runtime.h>
#include <cuda_fp16.h>
#include <math.h>
#include <stdint.h>

#define Dm 2048
#define Hn 16
#define Dh 128
#define Bb 2
#define Ll 2048
#define Mm (Bb*Ll)   /* 4096 rows */
#define SCALE_C 0.08838834764831845f   /* 1/sqrt(128) */

// ---------------- scratch (static device globals; no runtime allocation) ----
__device__ __half g_ahi[(size_t)Mm * Dm];   // x split hi, later O (single) 
__device__ __half g_alo[(size_t)Mm * Dm];   // x split lo
__device__ __half g_w[(size_t)4 * Dm * Dm]; // Wq,Wk,Wv,Wo single fp16
__device__ __half g_qhi[(size_t)Mm * Dm];
__device__ __half g_qlo[(size_t)Mm * Dm];
__device__ __half g_k[(size_t)Mm * Dm];     // K single fp16 (post-rope)
__device__ __half g_v[(size_t)Mm * Dm];     // V single fp16
__device__ float g_invf[Dh/2];

// ======================= helpers =============================================
__device__ __forceinline__ uint32_t smem_u32(const void* p) {
    uint32_t a;
    asm("{ .reg .u64 t; cvta.to.shared.u64 t, %1; cvt.u32.u64 %0, t; }"
        : "=r"(a) : "l"(p));
    return a;
}
__device__ __forceinline__ void cp_async16(uint32_t saddr, const void* gaddr) {
    asm volatile("cp.async.cg.shared.global [%0], [%1], 16;"
                 :: "r"(saddr), "l"(gaddr) : "memory");
}
#define CP_COMMIT() asm volatile("cp.async.commit_group;" ::: "memory")
#define CP_WAIT1()  asm volatile("cp.async.wait_group 1;" ::: "memory")
#define CP_WAIT0()  asm volatile("cp.async.wait_group 0;" ::: "memory")

__device__ __forceinline__ void ldsm4(uint32_t* d, uint32_t a) {
    asm volatile("ldmatrix.sync.aligned.m8n8.x4.shared.b16 {%0,%1,%2,%3}, [%4];"
                 : "=r"(d[0]), "=r"(d[1]), "=r"(d[2]), "=r"(d[3]) : "r"(a));
}
__device__ __forceinline__ void ldsm4t(uint32_t* d, uint32_t a) {
    asm volatile("ldmatrix.sync.aligned.m8n8.x4.trans.shared.b16 {%0,%1,%2,%3}, [%4];"
                 : "=r"(d[0]), "=r"(d[1]), "=r"(d[2]), "=r"(d[3]) : "r"(a));
}
__device__ __forceinline__ void mma16816(float* d, const uint32_t* a,
                                         uint32_t b0, uint32_t b1) {
    asm volatile(
        "mma.sync.aligned.m16n8k16.row.col.f32.f16.f16.f32 "
        "{%0,%1,%2,%3}, {%4,%5,%6,%7}, {%8,%9}, {%0,%1,%2,%3};"
        : "+f"(d[0]), "+f"(d[1]), "+f"(d[2]), "+f"(d[3])
        : "r"(a[0]), "r"(a[1]), "r"(a[2]), "r"(a[3]), "r"(b0), "r"(b1));
}
__device__ __forceinline__ uint32_t pack_hi2h(float a, float b) {
    __half2 t = __floats2half2_rn(a, b);
    return *reinterpret_cast<uint32_t*>(&t);
}
__device__ __forceinline__ uint32_t pack_lo2h(float a, float b) {
    float ra = a - __half2float(__float2half_rn(a));
    float rb = b - __half2float(__float2half_rn(b));
    __half2 t = __floats2half2_rn(ra, rb);
    return *reinterpret_cast<uint32_t*>(&t);
}

// ---------------- inv_freq table --------------------------------------------
__global__ void invf_kernel() {
    int i = threadIdx.x;
    if (i < Dh/2)
        g_invf[i] = (float)pow(10000.0, -(double)(2*i) / (double)Dh);
}

// ---------------- fp32 -> fp16 hi/lo split (x) --------------------------------
__global__ void split_x(const float4* __restrict__ src,
                        __half2* __restrict__ hi, __half2* __restrict__ lo, int n4)
{
    int i = blockIdx.x * blockDim.x + threadIdx.x;
    if (i >= n4) return;
    float4 v = src[i];
    uint32_t h0 = pack_hi2h(v.x, v.y), h1 = pack_hi2h(v.z, v.w);
    uint32_t l0 = pack_lo2h(v.x, v.y), l1 = pack_lo2h(v.z, v.w);
    hi[2*i]   = *reinterpret_cast<__half2*>(&h0);
    hi[2*i+1] = *reinterpret_cast<__half2*>(&h1);
    lo[2*i]   = *reinterpret_cast<__half2*>(&l0);
    lo[2*i+1] = *reinterpret_cast<__half2*>(&l1);
}

// ---------------- all 4 weights -> packed single fp16 ------------------------
__global__ void split4_w(const float4* __restrict__ w0, const float4* __restrict__ w1,
                         const float4* __restrict__ w2, const float4* __restrict__ w3,
                         __half2* __restrict__ w)
{
    const int n4each = (Dm * Dm) / 4;     // 2^20
    int idx = blockIdx.x * blockDim.x + threadIdx.x;
    int t = idx >> 20;
    int r = idx & (n4each - 1);
    const float4* s = (t == 0) ? w0 : (t == 1) ? w1 : (t == 2) ? w2 : w3;
    float4 v = s[r];
    w[2*(size_t)idx]   = __floats2half2_rn(v.x, v.y);
    w[2*(size_t)idx+1] = __floats2half2_rn(v.z, v.w);
}

// ==== GEMM mainloop (R11): CTA 128x64, 256 thr, 8 warps (4x2 of 32x32) =======
// per stage: Ahi(16K) + Alo(16K) + W(8K) = 40KB; 2 stages -> 83KB, 2 CTAs/SM
#define KC 64
#define TILE_A 16384
#define TILE_W 8192
#define STAGE_B (2*TILE_A + TILE_W)
#define GEMM_SMEM (1024 + 2*STAGE_B)

#define ISSUE_CHUNK(cc) do {                                                   \
    uint32_t sbase = su + ((cc) & 1) * STAGE_B;                                \
    const size_t kb = (size_t)(cc) * (KC * 2);                                 \
    _Pragma("unroll")                                                          \
    for (int t = 0; t < 2; t++) {                                              \
        const char* g = srcs[t] + kb;                                          \
        uint32_t s = sbase + t * TILE_A;                                       \
        _Pragma("unroll")                                                      \
        for (int i = 0; i < 4; i++) {                                          \
            int u = tid + (i << 8);                                            \
            int r = u >> 3;                                                    \
            int cb = (u & 7) << 4;                                             \
            uint32_t off = ((r >> 3) << 10) + ((r & 7) << 7) + (cb ^ ((r & 7) << 4)); \
            cp_async16(s + off, g + (size_t)r * rstride + cb);                 \
        }                                                                      \
    }                                                                          \
    {                                                                          \
        const char* g = srcs[2] + kb;                                          \
        uint32_t s = sbase + 2 * TILE_A;                                       \
        _Pragma("unroll")                                                      \
        for (int i = 0; i < 2; i++) {                                          \
            int u = tid + (i << 8);                                            \
            int r = u >> 3;                                                    \
            int cb = (u & 7) << 4;                                             \
            uint32_t off = ((r >> 3) << 10) + ((r & 7) << 7) + (cb ^ ((r & 7) << 4)); \
            cp_async16(s + off, g + (size_t)r * rstride + cb);                 \
        }                                                                      \
    }                                                                          \
    CP_COMMIT();                                                               \
} while (0)

#define GEMM_MAINLOOP()                                                        \
    uint32_t aoff[2], ar7[2];                                                  \
    _Pragma("unroll")                                                          \
    for (int m = 0; m < 2; m++) {                                              \
        int r = wm*32 + m*16 + (lane & 15);                                    \
        aoff[m] = ((r >> 3) << 10) + ((r & 7) << 7);                           \
        ar7[m]  = r & 7;                                                       \
    }                                                                          \
    uint32_t boff[4], br7[4];                                                  \
    _Pragma("unroll")                                                          \
    for (int n = 0; n < 4; n++) {                                              \
        int r = wn*32 + n*8 + (lane & 7);                                      \
        boff[n] = ((r >> 3) << 10) + ((r & 7) << 7);                           \
        br7[n]  = r & 7;                                                       \
    }                                                                          \
    const uint32_t uA_lo = lane >> 4;                                          \
    const uint32_t uB_lo = lane >> 3;                                          \
    float acc[2][4][4];                                                        \
    _Pragma("unroll")                                                          \
    for (int m = 0; m < 2; m++)                                                \
        _Pragma("unroll")                                                      \
        for (int n = 0; n < 4; n++)                                            \
            _Pragma("unroll")                                                  \
            for (int q = 0; q < 4; q++) acc[m][n][q] = 0.f;                    \
    const int NCH = Ko / KC;                                                   \
    ISSUE_CHUNK(0);                                                            \
    for (int c = 0; c < NCH; c++) {                                            \
        if (c + 1 < NCH) { ISSUE_CHUNK(c + 1); CP_WAIT1(); }                   \
        else { CP_WAIT0(); }                                                   \
        __syncthreads();                                                       \
        const uint32_t st  = su + (c & 1) * STAGE_B;                           \
        const uint32_t SAh = st;                                               \
        const uint32_t SAl = st + TILE_A;                                      \
        const uint32_t SB  = st + 2 * TILE_A;                                  \
        _Pragma("unroll")                                                      \
        for (int kp = 0; kp < 2; kp++) {                                       \
            uint32_t bb[4][4];                                                 \
            _Pragma("unroll")                                                  \
            for (int n = 0; n < 4; n++) {                                      \
                uint32_t uB = 4*kp + uB_lo;                                    \
                ldsm4(bb[n], SB + boff[n] + ((uB ^ br7[n]) << 4));             \
            }                                                                  \
            _Pragma("unroll")                                                  \
            for (int ki = 0; ki < 2; ki++) {                                   \
                uint32_t uA = 2*(2*kp + ki) + uA_lo;                           \
                uint32_t ah[2][4], al[2][4];                                   \
                _Pragma("unroll")                                              \
                for (int m = 0; m < 2; m++) {                                  \
                    ldsm4(ah[m], SAh + aoff[m] + ((uA ^ ar7[m]) << 4));        \
                    ldsm4(al[m], SAl + aoff[m] + ((uA ^ ar7[m]) << 4));        \
                }                                                              \
                _Pragma("unroll")                                              \
                for (int m = 0; m < 2; m++)                                    \
                    _Pragma("unroll")                                          \
                    for (int n = 0; n < 4; n++) {                              \
                        mma16816(acc[m][n], ah[m], bb[n][2*ki], bb[n][2*ki+1]); \
                        mma16816(acc[m][n], al[m], bb[n][2*ki], bb[n][2*ki+1]); \
                    }                                                          \
            }                                                                  \
        }                                                                      \
        __syncthreads();                                                       \
    }

// ---------------- fused QKV GEMM + RoPE + fp16 split epilogue ----------------
// grid (32, 32, 3): z=0 Q (rope+scale, hi/lo), z=1 K (rope), z=2 V
__global__ void __launch_bounds__(256, 2)
gemm_qkv(const __half* __restrict__ Ahi, const __half* __restrict__ Alo,
         const __half* __restrict__ W_all, const int* __restrict__ pos,
         __half* __restrict__ Qh, __half* __restrict__ Ql,
         __half* __restrict__ Kd, __half* __restrict__ Vd)
{
    extern __shared__ char smraw[];
    char* smal = (char*)(((uintptr_t)smraw + 1023) & ~(uintptr_t)1023);
    const uint32_t su = smem_u32(smal);

    const int tid = threadIdx.x;
    const int lane = tid & 31, wid = tid >> 5;
    const int row0 = blockIdx.y << 7;       // 128 rows per CTA
    const int col0 = blockIdx.x << 6;       // 64 cols per CTA
    const int z = blockIdx.z;
    const int wm = wid >> 1, wn = wid & 1;  // 4x2 warp grid, warp tile 32x32
    const int Ko = Dm;

    const char* srcs[3];
    srcs[0] = (const char*)(Ahi + (size_t)row0 * Ko);
    srcs[1] = (const char*)(Alo + (size_t)row0 * Ko);
    srcs[2] = (const char*)(W_all + (size_t)z * Dm * Dm + (size_t)col0 * Ko);
    const size_t rstride = (size_t)Ko * 2;

    GEMM_MAINLOOP();

    if (z == 2) {
#pragma unroll
        for (int m = 0; m < 2; m++) {
            int rw = row0 + wm*32 + m*16 + (lane >> 2);
#pragma unroll
            for (int n = 0; n < 4; n++) {
                int cw = col0 + wn*32 + n*8 + ((lane & 3) << 1);
                *(uint32_t*)(Vd + (size_t)rw * Dm + cw)     = pack_hi2h(acc[m][n][0], acc[m][n][1]);
                *(uint32_t*)(Vd + (size_t)(rw+8) * Dm + cw) = pack_hi2h(acc[m][n][2], acc[m][n][3]);
            }
        }
    } else if (z == 1) {
#pragma unroll
        for (int m = 0; m < 2; m++) {
            int rw = row0 + wm*32 + m*16 + (lane >> 2);
            float p0 = (float)pos[rw];
            float p1 = (float)pos[rw + 8];
#pragma unroll
            for (int n = 0; n < 4; n++) {
                int cw = col0 + wn*32 + n*8 + ((lane & 3) << 1);
                float inv = g_invf[(cw & 127) >> 1];
                float s0, c0, s1, c1;
                sincosf(p0 * inv, &s0, &c0);
                sincosf(p1 * inv, &s1, &c1);
                float e = acc[m][n][0], o = acc[m][n][1];
                *(uint32_t*)(Kd + (size_t)rw * Dm + cw) = pack_hi2h(e*c0 - o*s0, e*s0 + o*c0);
                e = acc[m][n][2]; o = acc[m][n][3];
                *(uint32_t*)(Kd + (size_t)(rw+8) * Dm + cw) = pack_hi2h(e*c1 - o*s1, e*s1 + o*c1);
            }
        }
    } else {
#pragma unroll
        for (int m = 0; m < 2; m++) {
            int rw = row0 + wm*32 + m*16 + (lane >> 2);
            float p0 = (float)pos[rw];
            float p1 = (float)pos[rw + 8];
#pragma unroll
            for (int n = 0; n < 4; n++) {
                int cw = col0 + wn*32 + n*8 + ((lane & 3) << 1);
                float inv = g_invf[(cw & 127) >> 1];
                float s0, c0, s1, c1;
                sincosf(p0 * inv, &s0, &c0);
                sincosf(p1 * inv, &s1, &c1);
                float e = acc[m][n][0], o = acc[m][n][1];
                float re = (e*c0 - o*s0) * SCALE_C, ro = (e*s0 + o*c0) * SCALE_C;
                *(uint32_t*)(Qh + (size_t)rw * Dm + cw) = pack_hi2h(re, ro);
                *(uint32_t*)(Ql + (size_t)rw * Dm + cw) = pack_lo2h(re, ro);
                e = acc[m][n][2]; o = acc[m][n][3];
                re = (e*c1 - o*s1) * SCALE_C; ro = (e*s1 + o*c1) * SCALE_C;
                *(uint32_t*)(Qh + (size_t)(rw+8) * Dm + cw) = pack_hi2h(re, ro);
                *(uint32_t*)(Ql + (size_t)(rw+8) * Dm + cw) = pack_lo2h(re, ro);
            }
        }
    }
}

// -------- single-pass fp16 GEMM (fp32 out) for the Wo projection -------------
// per stage: A(16K) + W(8K) = 24KB; 2 stages -> 50KB, 2 CTAs/SM (reg-capped)
#define G1_STAGE (TILE_A + TILE_W)
#define G1_SMEM (1024 + 2*G1_STAGE)

__global__ void __launch_bounds__(256, 2)
gemm_out(const __half* __restrict__ Ao, const __half* __restrict__ Bw,
         float* __restrict__ C, int Ko, int No)
{
    extern __shared__ char smraw[];
    char* smal = (char*)(((uintptr_t)smraw + 1023) & ~(uintptr_t)1023);
    const uint32_t su = smem_u32(smal);

    const int tid = threadIdx.x;
    const int lane = tid & 31, wid = tid >> 5;
    const int row0 = blockIdx.y << 7;
    const int col0 = blockIdx.x << 6;
    const int wm = wid >> 1, wn = wid & 1;

    const char* srcA = (const char*)(Ao + (size_t)row0 * Ko);
    const char* srcW = (const char*)(Bw + (size_t)col0 * Ko);
    const size_t rstride = (size_t)Ko * 2;

#define ISSUE1(cc) do {                                                        \
    uint32_t sbase = su + ((cc) & 1) * G1_STAGE;                               \
    const size_t kb = (size_t)(cc) * (KC * 2);                                 \
    {                                                                          \
        const char* g = srcA + kb;                                             \
        _Pragma("unroll")                                                      \
        for (int i = 0; i < 4; i++) {                                          \
            int u = tid + (i << 8);                                            \
            int r = u >> 3;                                                    \
            int cb = (u & 7) << 4;                                             \
            uint32_t off = ((r >> 3) << 10) + ((r & 7) << 7) + (cb ^ ((r & 7) << 4)); \
            cp_async16(sbase + off, g + (size_t)r * rstride + cb);             \
        }                                                                      \
    }                                                                          \
    {                                                                          \
        const char* g = srcW + kb;                                             \
        uint32_t s = sbase + TILE_A;                                           \
        _Pragma("unroll")                                                      \
        for (int i = 0; i < 2; i++) {                                          \
            int u = tid + (i << 8);                                            \
            int r = u >> 3;                                                    \
            int cb = (u & 7) << 4;                                             \
            uint32_t off = ((r >> 3) << 10) + ((r & 7) << 7) + (cb ^ ((r & 7) << 4)); \
            cp_async16(s + off, g + (size_t)r * rstride + cb);                 \
        }                                                                      \
    }                                                                          \
    CP_COMMIT();                                                               \
} while (0)

    uint32_t aoff[2], ar7[2];
#pragma unroll
    for (int m = 0; m < 2; m++) {
        int r = wm*32 + m*16 + (lane & 15);
        aoff[m] = ((r >> 3) << 10) + ((r & 7) << 7);
        ar7[m]  = r & 7;
    }
    uint32_t boff[4], br7[4];
#pragma unroll
    for (int n = 0; n < 4; n++) {
        int r = wn*32 + n*8 + (lane & 7);
        boff[n] = ((r >> 3) << 10) + ((r & 7) << 7);
        br7[n]  = r & 7;
    }
    const uint32_t uA_lo = lane >> 4;
    const uint32_t uB_lo = lane >> 3;
    float acc[2][4][4];
#pragma unroll
    for (int m = 0; m < 2; m++)
#pragma unroll
        for (int n = 0; n < 4; n++)
#pragma unroll
            for (int q = 0; q < 4; q++) acc[m][n][q] = 0.f;

    const int NCH = Ko / KC;
    ISSUE1(0);
    for (int c = 0; c < NCH; c++) {
        if (c + 1 < NCH) { ISSUE1(c + 1); CP_WAIT1(); }
        else { CP_WAIT0(); }
        __syncthreads();
        const uint32_t st = su + (c & 1) * G1_STAGE;
        const uint32_t SA = st;
        const uint32_t SB = st + TILE_A;
#pragma unroll
        for (int kp = 0; kp < 2; kp++) {
            uint32_t bb[4][4];
#pragma unroll
            for (int n = 0; n < 4; n++) {
                uint32_t uB = 4*kp + uB_lo;
                ldsm4(bb[n], SB + boff[n] + ((uB ^ br7[n]) << 4));
            }
#pragma unroll
            for (int ki = 0; ki < 2; ki++) {
                uint32_t uA = 2*(2*kp + ki) + uA_lo;
                uint32_t ah[2][4];
#pragma unroll
                for (int m = 0; m < 2; m++)
                    ldsm4(ah[m], SA + aoff[m] + ((uA ^ ar7[m]) << 4));
#pragma unroll
                for (int m = 0; m < 2; m++)
#pragma unroll
                    for (int n = 0; n < 4; n++)
                        mma16816(acc[m][n], ah[m], bb[n][2*ki], bb[n][2*ki+1]);
            }
        }
        __syncthreads();
    }

#pragma unroll
    for (int m = 0; m < 2; m++) {
        int rw = row0 + wm*32 + m*16 + (lane >> 2);
#pragma unroll
        for (int n = 0; n < 4; n++) {
            int cw = col0 + wn*32 + n*8 + ((lane & 3) << 1);
            *(float2*)(C + (size_t)rw * No + cw) =
                make_float2(acc[m][n][0], acc[m][n][1]);
            *(float2*)(C + (size_t)(rw + 8) * No + cw) =
                make_float2(acc[m][n][2], acc[m][n][3]);
        }
    }
}

// ---------------- tensor-core causal flash attention (fp16x2) ----------------
// SMEM: Qhi,Qlo (32KB) + K/V double-buffered (2 x 32KB) = 96KB, occ 2
#define ATT_SMEM 98304

#define ATT_ISSUE(kt) do {                                                     \
    const int kj0 = (kt) << 6;                                                 \
    uint32_t sb = su + 32768 + ((kt) & 1) * 32768;                             \
    _Pragma("unroll")                                                          \
    for (int i = 0; i < 8; i++) {                                              \
        int u = tid + (i << 7);                                                \
        int r = u >> 4, cu = u & 15;                                           \
        uint32_t so = r * 256 + ((cu ^ (r & 7)) << 4);                         \
        size_t go = (rowbase + kj0 + r) * Dm + hoff + cu * 8;                  \
        cp_async16(sb + so, K_g + go);                                         \
        cp_async16(sb + 16384 + so, V_g + go);                                 \
    }                                                                          \
    CP_COMMIT();                                                               \
} while (0)

__global__ void __launch_bounds__(128, 2)
attn_mma(const __half* __restrict__ Qh_g, const __half* __restrict__ Ql_g,
         const __half* __restrict__ K_g, const __half* __restrict__ V_g,
         __half* __restrict__ Od)
{
    extern __shared__ char sm[];
    const uint32_t su = smem_u32(sm);
    const uint32_t QH = 0, QL = 16384;

    const int tid = threadIdx.x, lane = tid & 31, wq = tid >> 5;
    const int qt = (int)(gridDim.x - 1 - blockIdx.x);
    const int h = blockIdx.y, b = blockIdx.z;
    const int qi0 = qt << 6;
    const size_t rowbase = (size_t)b * Ll;
    const int hoff = h * Dh;

    ATT_ISSUE(0);

#pragma unroll
    for (int i = 0; i < 8; i++) {
        int idx = tid + (i << 7);
        int r = idx >> 4, u = idx & 15;
        uint32_t so = r * 256 + ((u ^ (r & 7)) << 4);
        size_t go = (rowbase + qi0 + r) * Dm + hoff + u * 8;
        *(float4*)(sm + QH + so) = *(const float4*)(Qh_g + go);
        *(float4*)(sm + QL + so) = *(const float4*)(Ql_g + go);
    }

    float oacc[16][4];
#pragma unroll
    for (int t = 0; t < 16; t++)
#pragma unroll
        for (int q = 0; q < 4; q++) oacc[t][q] = 0.f;
    float m0 = -1e30f, m1 = -1e30f, l0 = 0.f, l1 = 0.f;

    for (int kt = 0; kt <= qt; kt++) {
        if (kt < qt) { ATT_ISSUE(kt + 1); CP_WAIT1(); }
        else { CP_WAIT0(); }
        __syncthreads();
        const uint32_t KS = su + 32768 + (kt & 1) * 32768;
        const uint32_t VS = KS + 16384;

        // ---- S = Q K^T (fp16x2: Qhi*K + Qlo*K)
        float sacc[8][4];
#pragma unroll
        for (int n = 0; n < 8; n++)
#pragma unroll
            for (int q = 0; q < 4; q++) sacc[n][q] = 0.f;

#pragma unroll
        for (int kg = 0; kg < 4; kg++) {
            uint32_t bk[8][4];
#pragma unroll
            for (int n = 0; n < 8; n++) {
                int r = (n << 3) + (lane & 7);
                int u = (kg << 2) + (lane >> 3);
                ldsm4(bk[n], KS + r * 256 + ((u ^ (r & 7)) << 4));
            }
#pragma unroll
            for (int ki = 0; ki < 2; ki++) {
                int r = (wq << 4) + (lane & 15);
                int u = ((2 * kg + ki) << 1) + (lane >> 4);
                uint32_t o = r * 256 + ((u ^ (r & 7)) << 4);
                uint32_t ah[4], al[4];
                ldsm4(ah, su + QH + o);
                ldsm4(al, su + QL + o);
#pragma unroll
                for (int n = 0; n < 8; n++) {
                    mma16816(sacc[n], ah, bk[n][2*ki], bk[n][2*ki+1]);
                    mma16816(sacc[n], al, bk[n][2*ki], bk[n][2*ki+1]);
                }
            }
        }

        if (kt == qt) {
            int r0 = (wq << 4) + (lane >> 2), r1 = r0 + 8;
            int cb = 2 * (lane & 3);
#pragma unroll
            for (int n = 0; n < 8; n++) {
                int c0 = (n << 3) + cb, c1 = c0 + 1;
                if (c0 > r0) sacc[n][0] = -1e30f;
                if (c1 > r0) sacc[n][1] = -1e30f;
                if (c0 > r1) sacc[n][2] = -1e30f;
                if (c1 > r1) sacc[n][3] = -1e30f;
            }
        }

        float mx0 = -1e30f, mx1 = -1e30f;
#pragma unroll
        for (int n = 0; n < 8; n++) {
            mx0 = fmaxf(mx0, fmaxf(sacc[n][0], sacc[n][1]));
            mx1 = fmaxf(mx1, fmaxf(sacc[n][2], sacc[n][3]));
        }
        mx0 = fmaxf(mx0, __shfl_xor_sync(0xffffffffu, mx0, 1));
        mx0 = fmaxf(mx0, __shfl_xor_sync(0xffffffffu, mx0, 2));
        mx1 = fmaxf(mx1, __shfl_xor_sync(0xffffffffu, mx1, 1));
        mx1 = fmaxf(mx1, __shfl_xor_sync(0xffffffffu, mx1, 2));
        float mn0 = fmaxf(m0, mx0), mn1 = fmaxf(m1, mx1);
        float al0 = __expf(m0 - mn0), al1 = __expf(m1 - mn1);
        float s0 = 0.f, s1 = 0.f;
#pragma unroll
        for (int n = 0; n < 8; n++) {
            sacc[n][0] = __expf(sacc[n][0] - mn0);
            sacc[n][1] = __expf(sacc[n][1] - mn0);
            sacc[n][2] = __expf(sacc[n][2] - mn1);
            sacc[n][3] = __expf(sacc[n][3] - mn1);
            s0 += sacc[n][0] + sacc[n][1];
            s1 += sacc[n][2] + sacc[n][3];
        }
        s0 += __shfl_xor_sync(0xffffffffu, s0, 1);
        s0 += __shfl_xor_sync(0xffffffffu, s0, 2);
        s1 += __shfl_xor_sync(0xffffffffu, s1, 1);
        s1 += __shfl_xor_sync(0xffffffffu, s1, 2);
        l0 = l0 * al0 + s0; l1 = l1 * al1 + s1;
        m0 = mn0; m1 = mn1;
#pragma unroll
        for (int t = 0; t < 16; t++) {
            oacc[t][0] *= al0; oacc[t][1] *= al0;
            oacc[t][2] *= al1; oacc[t][3] *= al1;
        }

        // ---- O += P V
#pragma unroll
        for (int ks = 0; ks < 4; ks++) {
            uint32_t ph[4], pl[4];
            ph[0] = pack_hi2h(sacc[2*ks][0],   sacc[2*ks][1]);
            ph[1] = pack_hi2h(sacc[2*ks][2],   sacc[2*ks][3]);
            ph[2] = pack_hi2h(sacc[2*ks+1][0], sacc[2*ks+1][1]);
            ph[3] = pack_hi2h(sacc[2*ks+1][2], sacc[2*ks+1][3]);
            pl[0] = pack_lo2h(sacc[2*ks][0],   sacc[2*ks][1]);
            pl[1] = pack_lo2h(sacc[2*ks][2],   sacc[2*ks][3]);
            pl[2] = pack_lo2h(sacc[2*ks+1][0], sacc[2*ks+1][1]);
            pl[3] = pack_lo2h(sacc[2*ks+1][2], sacc[2*ks+1][3]);
#pragma unroll
            for (int dg = 0; dg < 8; dg++) {
                int r = (ks << 4) + (lane & 15);
                int u = (dg << 1) + (lane >> 4);
                uint32_t bv[4];
                ldsm4t(bv, VS + r * 256 + ((u ^ (r & 7)) << 4));
                mma16816(oacc[2*dg],   ph, bv[0], bv[1]);
                mma16816(oacc[2*dg+1], ph, bv[2], bv[3]);
                mma16816(oacc[2*dg],   pl, bv[0], bv[1]);
                mma16816(oacc[2*dg+1], pl, bv[2], bv[3]);
            }
        }
        __syncthreads();
    }

    // ---- epilogue: O/l -> single fp16 (error budget spent here deliberately)
    float i0 = 1.f / l0, i1 = 1.f / l1;
    size_t grow0 = rowbase + qi0 + (wq << 4) + (lane >> 2);
    size_t grow1 = grow0 + 8;
    int cb = hoff + 2 * (lane & 3);
#pragma unroll
    for (int t = 0; t < 16; t++) {
        int col = cb + (t << 3);
        *(uint32_t*)(Od + grow0 * Dm + col) = pack_hi2h(oacc[t][0] * i0, oacc[t][1] * i0);
        *(uint32_t*)(Od + grow1 * Dm + col) = pack_hi2h(oacc[t][2] * i1, oacc[t][3] * i1);
    }
}

// ---------------- launch ------------------------------------------------------
extern "C" void kernel_launch(void* const* d_in, const int* in_sizes, int n_in,
                              void* d_out, int out_size)
{
    const float* x  = (const float*)d_in[0];
    const int*  pos = (const int*)d_in[1];
    const float* Wq = (const float*)d_in[2];
    const float* Wk = (const float*)d_in[3];
    const float* Wv = (const float*)d_in[4];
    const float* Wo = (const float*)d_in[5];
    float* out = (float*)d_out;

    __half *ahi, *alo, *w, *qhi, *qlo, *kd, *vd;
    cudaGetSymbolAddress((void**)&ahi, g_ahi);
    cudaGetSymbolAddress((void**)&alo, g_alo);
    cudaGetSymbolAddress((void**)&w,   g_w);
    cudaGetSymbolAddress((void**)&qhi, g_qhi);
    cudaGetSymbolAddress((void**)&qlo, g_qlo);
    cudaGetSymbolAddress((void**)&kd,  g_k);
    cudaGetSymbolAddress((void**)&vd,  g_v);

    invf_kernel<<<1, 64>>>();

    const int nx4 = (Mm * Dm) / 4;
    const int nw4 = (Dm * Dm) / 4;

    cudaFuncSetAttribute(gemm_qkv,
                         cudaFuncAttributeMaxDynamicSharedMemorySize, GEMM_SMEM);
    cudaFuncSetAttribute(gemm_out,
                         cudaFuncAttributeMaxDynamicSharedMemorySize, G1_SMEM);
    cudaFuncSetAttribute(attn_mma,
                         cudaFuncAttributeMaxDynamicSharedMemorySize, ATT_SMEM);

    // x -> fp16 hi/lo
    split_x<<<nx4/256, 256>>>((const float4*)x, (__half2*)ahi, (__half2*)alo, nx4);
    // all 4 weights -> packed single fp16
    split4_w<<<(4*nw4)/256, 256>>>((const float4*)Wq, (const float4*)Wk,
                                   (const float4*)Wv, (const float4*)Wo, (__half2*)w);

    // fused QKV GEMM + RoPE + split (one launch, 3072 CTAs, 256 thr, 2 CTA/SM)
    dim3 qkvgrid(Dm/64, Mm/128, 3);
    gemm_qkv<<<qkvgrid, 256, GEMM_SMEM>>>(ahi, alo, w, pos, qhi, qlo, kd, vd);

    // attention -> O single fp16 into g_ahi
    dim3 agrid(Ll/64, Hn, Bb);
    attn_mma<<<agrid, 128, ATT_SMEM>>>(qhi, qlo, kd, vd, ahi);

    // out = O Wo^T (fp32, single-pass)
    dim3 ggrid(Dm/64, Mm/128);
    gemm_out<<<ggrid, 256, G1_SMEM>>>(ahi, w + (size_t)3*Dm*Dm, out, Dm, Dm);
}

// round 14
// speedup vs baseline: 1.3237x; 1.2048x over previous
#include <cuda_runtime.h>
#include <cuda_fp16.h>
#include <math.h>
#include <stdint.h>

#define Dm 2048
#define Hn 16
#define Dh 128
#define Bb 2
#define Ll 2048
#define Mm (Bb*Ll)   /* 4096 rows */
#define SCALE_C 0.08838834764831845f   /* 1/sqrt(128) */

// ---------------- scratch (static device globals; no runtime allocation) ----
__device__ __half g_ahi[(size_t)Mm * Dm];   // x split hi, later O (single)
__device__ __half g_alo[(size_t)Mm * Dm];   // x split lo
__device__ __half g_w[(size_t)4 * Dm * Dm]; // Wq,Wk,Wv,Wo single fp16
__device__ __half g_qhi[(size_t)Mm * Dm];
__device__ __half g_qlo[(size_t)Mm * Dm];
__device__ __half g_k[(size_t)Mm * Dm];     // K single fp16 (post-rope)
__device__ __half g_v[(size_t)Mm * Dm];     // V single fp16
__device__ float g_invf[Dh/2];

// ======================= helpers =============================================
__device__ __forceinline__ uint32_t smem_u32(const void* p) {
    uint32_t a;
    asm("{ .reg .u64 t; cvta.to.shared.u64 t, %1; cvt.u32.u64 %0, t; }"
        : "=r"(a) : "l"(p));
    return a;
}
__device__ __forceinline__ void cp_async16(uint32_t saddr, const void* gaddr) {
    asm volatile("cp.async.cg.shared.global [%0], [%1], 16;"
                 :: "r"(saddr), "l"(gaddr) : "memory");
}
#define CP_COMMIT() asm volatile("cp.async.commit_group;" ::: "memory")
#define CP_WAIT1()  asm volatile("cp.async.wait_group 1;" ::: "memory")
#define CP_WAIT0()  asm volatile("cp.async.wait_group 0;" ::: "memory")

__device__ __forceinline__ void ldsm4(uint32_t* d, uint32_t a) {
    asm volatile("ldmatrix.sync.aligned.m8n8.x4.shared.b16 {%0,%1,%2,%3}, [%4];"
                 : "=r"(d[0]), "=r"(d[1]), "=r"(d[2]), "=r"(d[3]) : "r"(a));
}
__device__ __forceinline__ void ldsm4t(uint32_t* d, uint32_t a) {
    asm volatile("ldmatrix.sync.aligned.m8n8.x4.trans.shared.b16 {%0,%1,%2,%3}, [%4];"
                 : "=r"(d[0]), "=r"(d[1]), "=r"(d[2]), "=r"(d[3]) : "r"(a));
}
__device__ __forceinline__ void mma16816(float* d, const uint32_t* a,
                                         uint32_t b0, uint32_t b1) {
    asm volatile(
        "mma.sync.aligned.m16n8k16.row.col.f32.f16.f16.f32 "
        "{%0,%1,%2,%3}, {%4,%5,%6,%7}, {%8,%9}, {%0,%1,%2,%3};"
        : "+f"(d[0]), "+f"(d[1]), "+f"(d[2]), "+f"(d[3])
        : "r"(a[0]), "r"(a[1]), "r"(a[2]), "r"(a[3]), "r"(b0), "r"(b1));
}
__device__ __forceinline__ uint32_t pack_hi2h(float a, float b) {
    __half2 t = __floats2half2_rn(a, b);
    return *reinterpret_cast<uint32_t*>(&t);
}
__device__ __forceinline__ uint32_t pack_lo2h(float a, float b) {
    float ra = a - __half2float(__float2half_rn(a));
    float rb = b - __half2float(__float2half_rn(b));
    __half2 t = __floats2half2_rn(ra, rb);
    return *reinterpret_cast<uint32_t*>(&t);
}

// ---------------- inv_freq table --------------------------------------------
__global__ void invf_kernel() {
    int i = threadIdx.x;
    if (i < Dh/2)
        g_invf[i] = (float)pow(10000.0, -(double)(2*i) / (double)Dh);
}

// ---------------- fp32 -> fp16 hi/lo split (x) --------------------------------
__global__ void split_x(const float4* __restrict__ src,
                        __half2* __restrict__ hi, __half2* __restrict__ lo, int n4)
{
    int i = blockIdx.x * blockDim.x + threadIdx.x;
    if (i >= n4) return;
    float4 v = src[i];
    uint32_t h0 = pack_hi2h(v.x, v.y), h1 = pack_hi2h(v.z, v.w);
    uint32_t l0 = pack_lo2h(v.x, v.y), l1 = pack_lo2h(v.z, v.w);
    hi[2*i]   = *reinterpret_cast<__half2*>(&h0);
    hi[2*i+1] = *reinterpret_cast<__half2*>(&h1);
    lo[2*i]   = *reinterpret_cast<__half2*>(&l0);
    lo[2*i+1] = *reinterpret_cast<__half2*>(&l1);
}

// ---------------- all 4 weights -> packed single fp16 ------------------------
__global__ void split4_w(const float4* __restrict__ w0, const float4* __restrict__ w1,
                         const float4* __restrict__ w2, const float4* __restrict__ w3,
                         __half2* __restrict__ w)
{
    const int n4each = (Dm * Dm) / 4;     // 2^20
    int idx = blockIdx.x * blockDim.x + threadIdx.x;
    int t = idx >> 20;
    int r = idx & (n4each - 1);
    const float4* s = (t == 0) ? w0 : (t == 1) ? w1 : (t == 2) ? w2 : w3;
    float4 v = s[r];
    w[2*(size_t)idx]   = __floats2half2_rn(v.x, v.y);
    w[2*(size_t)idx+1] = __floats2half2_rn(v.z, v.w);
}

// ==== GEMM tiles: CTA 128x64, 256 thr, 8 warps (4x2 of 32x32), 2 stages ======
#define KC 64
#define TILE_A 16384
#define TILE_W 8192
#define STAGE_B (2*TILE_A + TILE_W)     /* hi/lo: Ahi+Alo+W = 40KB */
#define GEMM_SMEM (1024 + 2*STAGE_B)
#define G1_STAGE (TILE_A + TILE_W)      /* single: A+W = 24KB */
#define G1_SMEM (1024 + 2*G1_STAGE)

// ---- 2-pass (hi/lo) issue+mainloop: needs srcs[3], declares acc -------------
#define ISSUE_CHUNK(cc) do {                                                   \
    uint32_t sbase = su + ((cc) & 1) * STAGE_B;                                \
    const size_t kb = (size_t)(cc) * (KC * 2);                                 \
    _Pragma("unroll")                                                          \
    for (int t = 0; t < 2; t++) {                                              \
        const char* g = srcs[t] + kb;                                          \
        uint32_t s = sbase + t * TILE_A;                                       \
        _Pragma("unroll")                                                      \
        for (int i = 0; i < 4; i++) {                                          \
            int u = tid + (i << 8);                                            \
            int r = u >> 3;                                                    \
            int cb = (u & 7) << 4;                                             \
            uint32_t off = ((r >> 3) << 10) + ((r & 7) << 7) + (cb ^ ((r & 7) << 4)); \
            cp_async16(s + off, g + (size_t)r * rstride + cb);                 \
        }                                                                      \
    }                                                                          \
    {                                                                          \
        const char* g = srcs[2] + kb;                                          \
        uint32_t s = sbase + 2 * TILE_A;                                       \
        _Pragma("unroll")                                                      \
        for (int i = 0; i < 2; i++) {                                          \
            int u = tid + (i << 8);                                            \
            int r = u >> 3;                                                    \
            int cb = (u & 7) << 4;                                             \
            uint32_t off = ((r >> 3) << 10) + ((r & 7) << 7) + (cb ^ ((r & 7) << 4)); \
            cp_async16(s + off, g + (size_t)r * rstride + cb);                 \
        }                                                                      \
    }                                                                          \
    CP_COMMIT();                                                               \
} while (0)

#define FRAG_SETUP()                                                           \
    uint32_t aoff[2], ar7[2];                                                  \
    _Pragma("unroll")                                                          \
    for (int m = 0; m < 2; m++) {                                              \
        int r = wm*32 + m*16 + (lane & 15);                                    \
        aoff[m] = ((r >> 3) << 10) + ((r & 7) << 7);                           \
        ar7[m]  = r & 7;                                                       \
    }                                                                          \
    uint32_t boff[4], br7[4];                                                  \
    _Pragma("unroll")                                                          \
    for (int n = 0; n < 4; n++) {                                              \
        int r = wn*32 + n*8 + (lane & 7);                                      \
        boff[n] = ((r >> 3) << 10) + ((r & 7) << 7);                           \
        br7[n]  = r & 7;                                                       \
    }                                                                          \
    const uint32_t uA_lo = lane >> 4;                                          \
    const uint32_t uB_lo = lane >> 3;                                          \
    float acc[2][4][4];                                                        \
    _Pragma("unroll")                                                          \
    for (int m = 0; m < 2; m++)                                                \
        _Pragma("unroll")                                                      \
        for (int n = 0; n < 4; n++)                                            \
            _Pragma("unroll")                                                  \
            for (int q = 0; q < 4; q++) acc[m][n][q] = 0.f;

#define GEMM_MAINLOOP()                                                        \
    FRAG_SETUP();                                                              \
    const int NCH = Ko / KC;                                                   \
    ISSUE_CHUNK(0);                                                            \
    for (int c = 0; c < NCH; c++) {                                            \
        if (c + 1 < NCH) { ISSUE_CHUNK(c + 1); CP_WAIT1(); }                   \
        else { CP_WAIT0(); }                                                   \
        __syncthreads();                                                       \
        const uint32_t st  = su + (c & 1) * STAGE_B;                           \
        const uint32_t SAh = st;                                               \
        const uint32_t SAl = st + TILE_A;                                      \
        const uint32_t SB  = st + 2 * TILE_A;                                  \
        _Pragma("unroll")                                                      \
        for (int kp = 0; kp < 2; kp++) {                                       \
            uint32_t bb[4][4];                                                 \
            _Pragma("unroll")                                                  \
            for (int n = 0; n < 4; n++) {                                      \
                uint32_t uB = 4*kp + uB_lo;                                    \
                ldsm4(bb[n], SB + boff[n] + ((uB ^ br7[n]) << 4));             \
            }                                                                  \
            _Pragma("unroll")                                                  \
            for (int ki = 0; ki < 2; ki++) {                                   \
                uint32_t uA = 2*(2*kp + ki) + uA_lo;                           \
                uint32_t ah[2][4], al[2][4];                                   \
                _Pragma("unroll")                                              \
                for (int m = 0; m < 2; m++) {                                  \
                    ldsm4(ah[m], SAh + aoff[m] + ((uA ^ ar7[m]) << 4));        \
                    ldsm4(al[m], SAl + aoff[m] + ((uA ^ ar7[m]) << 4));        \
                }                                                              \
                _Pragma("unroll")                                              \
                for (int m = 0; m < 2; m++)                                    \
                    _Pragma("unroll")                                          \
                    for (int n = 0; n < 4; n++) {                              \
                        mma16816(acc[m][n], ah[m], bb[n][2*ki], bb[n][2*ki+1]); \
                        mma16816(acc[m][n], al[m], bb[n][2*ki], bb[n][2*ki+1]); \
                    }                                                          \
            }                                                                  \
        }                                                                      \
        __syncthreads();                                                       \
    }

// ---- single-pass issue+mainloop: needs srcA/srcW, declares acc --------------
#define ISSUE1(cc) do {                                                        \
    uint32_t sbase = su + ((cc) & 1) * G1_STAGE;                               \
    const size_t kb = (size_t)(cc) * (KC * 2);                                 \
    {                                                                          \
        const char* g = srcA + kb;                                             \
        _Pragma("unroll")                                                      \
        for (int i = 0; i < 4; i++) {                                          \
            int u = tid + (i << 8);                                            \
            int r = u >> 3;                                                    \
            int cb = (u & 7) << 4;                                             \
            uint32_t off = ((r >> 3) << 10) + ((r & 7) << 7) + (cb ^ ((r & 7) << 4)); \
            cp_async16(sbase + off, g + (size_t)r * rstride + cb);             \
        }                                                                      \
    }                                                                          \
    {                                                                          \
        const char* g = srcW + kb;                                             \
        uint32_t s = sbase + TILE_A;                                           \
        _Pragma("unroll")                                                      \
        for (int i = 0; i < 2; i++) {                                          \
            int u = tid + (i << 8);                                            \
            int r = u >> 3;                                                    \
            int cb = (u & 7) << 4;                                             \
            uint32_t off = ((r >> 3) << 10) + ((r & 7) << 7) + (cb ^ ((r & 7) << 4)); \
            cp_async16(s + off, g + (size_t)r * rstride + cb);                 \
        }                                                                      \
    }                                                                          \
    CP_COMMIT();                                                               \
} while (0)

#define GEMM_MAINLOOP1()                                                       \
    FRAG_SETUP();                                                              \
    const int NCH = Ko / KC;                                                   \
    ISSUE1(0);                                                                 \
    for (int c = 0; c < NCH; c++) {                                            \
        if (c + 1 < NCH) { ISSUE1(c + 1); CP_WAIT1(); }                        \
        else { CP_WAIT0(); }                                                   \
        __syncthreads();                                                       \
        const uint32_t st = su + (c & 1) * G1_STAGE;                           \
        const uint32_t SA = st;                                                \
        const uint32_t SB = st + TILE_A;                                       \
        _Pragma("unroll")                                                      \
        for (int kp = 0; kp < 2; kp++) {                                       \
            uint32_t bb[4][4];                                                 \
            _Pragma("unroll")                                                  \
            for (int n = 0; n < 4; n++) {                                      \
                uint32_t uB = 4*kp + uB_lo;                                    \
                ldsm4(bb[n], SB + boff[n] + ((uB ^ br7[n]) << 4));             \
            }                                                                  \
            _Pragma("unroll")                                                  \
            for (int ki = 0; ki < 2; ki++) {                                   \
                uint32_t uA = 2*(2*kp + ki) + uA_lo;                           \
                uint32_t ah[2][4];                                             \
                _Pragma("unroll")                                              \
                for (int m = 0; m < 2; m++)                                    \
                    ldsm4(ah[m], SA + aoff[m] + ((uA ^ ar7[m]) << 4));         \
                _Pragma("unroll")                                              \
                for (int m = 0; m < 2; m++)                                    \
                    _Pragma("unroll")                                          \
                    for (int n = 0; n < 4; n++)                                \
                        mma16816(acc[m][n], ah[m], bb[n][2*ki], bb[n][2*ki+1]); \
            }                                                                  \
        }                                                                      \
        __syncthreads();                                                       \
    }

// ---------------- fused QKV GEMM + RoPE + fp16 split epilogue ----------------
// grid (32, 32, 3): z=0 Q (2-pass, rope+scale, hi/lo out),
//                   z=1 K (1-pass, rope, single), z=2 V (1-pass, single)
__global__ void __launch_bounds__(256, 2)
gemm_qkv(const __half* __restrict__ Ahi, const __half* __restrict__ Alo,
         const __half* __restrict__ W_all, const int* __restrict__ pos,
         __half* __restrict__ Qh, __half* __restrict__ Ql,
         __half* __restrict__ Kd, __half* __restrict__ Vd)
{
    extern __shared__ char smraw[];
    char* smal = (char*)(((uintptr_t)smraw + 1023) & ~(uintptr_t)1023);
    const uint32_t su = smem_u32(smal);

    const int tid = threadIdx.x;
    const int lane = tid & 31, wid = tid >> 5;
    const int row0 = blockIdx.y << 7;       // 128 rows per CTA
    const int col0 = blockIdx.x << 6;       // 64 cols per CTA
    const int z = blockIdx.z;
    const int wm = wid >> 1, wn = wid & 1;  // 4x2 warp grid, warp tile 32x32
    const int Ko = Dm;
    const size_t rstride = (size_t)Ko * 2;

    if (z == 0) {
        // ---- Q: 2-pass (x_hi + x_lo), RoPE + scale, hi/lo output
        const char* srcs[3];
        srcs[0] = (const char*)(Ahi + (size_t)row0 * Ko);
        srcs[1] = (const char*)(Alo + (size_t)row0 * Ko);
        srcs[2] = (const char*)(W_all + (size_t)col0 * Ko);

        GEMM_MAINLOOP();

#pragma unroll
        for (int m = 0; m < 2; m++) {
            int rw = row0 + wm*32 + m*16 + (lane >> 2);
            float p0 = (float)pos[rw];
            float p1 = (float)pos[rw + 8];
#pragma unroll
            for (int n = 0; n < 4; n++) {
                int cw = col0 + wn*32 + n*8 + ((lane & 3) << 1);
                float inv = g_invf[(cw & 127) >> 1];
                float s0, c0, s1, c1;
                sincosf(p0 * inv, &s0, &c0);
                sincosf(p1 * inv, &s1, &c1);
                float e = acc[m][n][0], o = acc[m][n][1];
                float re = (e*c0 - o*s0) * SCALE_C, ro = (e*s0 + o*c0) * SCALE_C;
                *(uint32_t*)(Qh + (size_t)rw * Dm + cw) = pack_hi2h(re, ro);
                *(uint32_t*)(Ql + (size_t)rw * Dm + cw) = pack_lo2h(re, ro);
                e = acc[m][n][2]; o = acc[m][n][3];
                re = (e*c1 - o*s1) * SCALE_C; ro = (e*s1 + o*c1) * SCALE_C;
                *(uint32_t*)(Qh + (size_t)(rw+8) * Dm + cw) = pack_hi2h(re, ro);
                *(uint32_t*)(Ql + (size_t)(rw+8) * Dm + cw) = pack_lo2h(re, ro);
            }
        }
    } else {
        // ---- K/V: single-pass (x_hi only)
        const char* srcA = (const char*)(Ahi + (size_t)row0 * Ko);
        const char* srcW = (const char*)(W_all + (size_t)z * Dm * Dm + (size_t)col0 * Ko);

        GEMM_MAINLOOP1();

        if (z == 1) {
#pragma unroll
            for (int m = 0; m < 2; m++) {
                int rw = row0 + wm*32 + m*16 + (lane >> 2);
                float p0 = (float)pos[rw];
                float p1 = (float)pos[rw + 8];
#pragma unroll
                for (int n = 0; n < 4; n++) {
                    int cw = col0 + wn*32 + n*8 + ((lane & 3) << 1);
                    float inv = g_invf[(cw & 127) >> 1];
                    float s0, c0, s1, c1;
                    sincosf(p0 * inv, &s0, &c0);
                    sincosf(p1 * inv, &s1, &c1);
                    float e = acc[m][n][0], o = acc[m][n][1];
                    *(uint32_t*)(Kd + (size_t)rw * Dm + cw) = pack_hi2h(e*c0 - o*s0, e*s0 + o*c0);
                    e = acc[m][n][2]; o = acc[m][n][3];
                    *(uint32_t*)(Kd + (size_t)(rw+8) * Dm + cw) = pack_hi2h(e*c1 - o*s1, e*s1 + o*c1);
                }
            }
        } else {
#pragma unroll
            for (int m = 0; m < 2; m++) {
                int rw = row0 + wm*32 + m*16 + (lane >> 2);
#pragma unroll
                for (int n = 0; n < 4; n++) {
                    int cw = col0 + wn*32 + n*8 + ((lane & 3) << 1);
                    *(uint32_t*)(Vd + (size_t)rw * Dm + cw)     = pack_hi2h(acc[m][n][0], acc[m][n][1]);
                    *(uint32_t*)(Vd + (size_t)(rw+8) * Dm + cw) = pack_hi2h(acc[m][n][2], acc[m][n][3]);
                }
            }
        }
    }
}

// -------- single-pass fp16 GEMM (fp32 out) for the Wo projection -------------
__global__ void __launch_bounds__(256, 2)
gemm_out(const __half* __restrict__ Ao, const __half* __restrict__ Bw,
         float* __restrict__ C, int Ko, int No)
{
    extern __shared__ char smraw[];
    char* smal = (char*)(((uintptr_t)smraw + 1023) & ~(uintptr_t)1023);
    const uint32_t su = smem_u32(smal);

    const int tid = threadIdx.x;
    const int lane = tid & 31, wid = tid >> 5;
    const int row0 = blockIdx.y << 7;
    const int col0 = blockIdx.x << 6;
    const int wm = wid >> 1, wn = wid & 1;

    const char* srcA = (const char*)(Ao + (size_t)row0 * Ko);
    const char* srcW = (const char*)(Bw + (size_t)col0 * Ko);
    const size_t rstride = (size_t)Ko * 2;

    GEMM_MAINLOOP1();

#pragma unroll
    for (int m = 0; m < 2; m++) {
        int rw = row0 + wm*32 + m*16 + (lane >> 2);
#pragma unroll
        for (int n = 0; n < 4; n++) {
            int cw = col0 + wn*32 + n*8 + ((lane & 3) << 1);
            *(float2*)(C + (size_t)rw * No + cw) =
                make_float2(acc[m][n][0], acc[m][n][1]);
            *(float2*)(C + (size_t)(rw + 8) * No + cw) =
                make_float2(acc[m][n][2], acc[m][n][3]);
        }
    }
}

// ---------------- tensor-core causal flash attention (fp16x2) ----------------
// SMEM: Qhi,Qlo (32KB) + K/V double-buffered (2 x 32KB) = 96KB, occ 2
#define ATT_SMEM 98304

#define ATT_ISSUE(kt) do {                                                     \
    const int kj0 = (kt) << 6;                                                 \
    uint32_t sb = su + 32768 + ((kt) & 1) * 32768;                             \
    _Pragma("unroll")                                                          \
    for (int i = 0; i < 8; i++) {                                              \
        int u = tid + (i << 7);                                                \
        int r = u >> 4, cu = u & 15;                                           \
        uint32_t so = r * 256 + ((cu ^ (r & 7)) << 4);                         \
        size_t go = (rowbase + kj0 + r) * Dm + hoff + cu * 8;                  \
        cp_async16(sb + so, K_g + go);                                         \
        cp_async16(sb + 16384 + so, V_g + go);                                 \
    }                                                                          \
    CP_COMMIT();                                                               \
} while (0)

__global__ void __launch_bounds__(128, 2)
attn_mma(const __half* __restrict__ Qh_g, const __half* __restrict__ Ql_g,
         const __half* __restrict__ K_g, const __half* __restrict__ V_g,
         __half* __restrict__ Od)
{
    extern __shared__ char sm[];
    const uint32_t su = smem_u32(sm);
    const uint32_t QH = 0, QL = 16384;

    const int tid = threadIdx.x, lane = tid & 31, wq = tid >> 5;
    const int qt = (int)(gridDim.x - 1 - blockIdx.x);
    const int h = blockIdx.y, b = blockIdx.z;
    const int qi0 = qt << 6;
    const size_t rowbase = (size_t)b * Ll;
    const int hoff = h * Dh;

    ATT_ISSUE(0);

#pragma unroll
    for (int i = 0; i < 8; i++) {
        int idx = tid + (i << 7);
        int r = idx >> 4, u = idx & 15;
        uint32_t so = r * 256 + ((u ^ (r & 7)) << 4);
        size_t go = (rowbase + qi0 + r) * Dm + hoff + u * 8;
        *(float4*)(sm + QH + so) = *(const float4*)(Qh_g + go);
        *(float4*)(sm + QL + so) = *(const float4*)(Ql_g + go);
    }

    float oacc[16][4];
#pragma unroll
    for (int t = 0; t < 16; t++)
#pragma unroll
        for (int q = 0; q < 4; q++) oacc[t][q] = 0.f;
    float m0 = -1e30f, m1 = -1e30f, l0 = 0.f, l1 = 0.f;

    for (int kt = 0; kt <= qt; kt++) {
        if (kt < qt) { ATT_ISSUE(kt + 1); CP_WAIT1(); }
        else { CP_WAIT0(); }
        __syncthreads();
        const uint32_t KS = su + 32768 + (kt & 1) * 32768;
        const uint32_t VS = KS + 16384;

        // ---- S = Q K^T (fp16x2: Qhi*K + Qlo*K)
        float sacc[8][4];
#pragma unroll
        for (int n = 0; n < 8; n++)
#pragma unroll
            for (int q = 0; q < 4; q++) sacc[n][q] = 0.f;

#pragma unroll
        for (int kg = 0; kg < 4; kg++) {
            uint32_t bk[8][4];
#pragma unroll
            for (int n = 0; n < 8; n++) {
                int r = (n << 3) + (lane & 7);
                int u = (kg << 2) + (lane >> 3);
                ldsm4(bk[n], KS + r * 256 + ((u ^ (r & 7)) << 4));
            }
#pragma unroll
            for (int ki = 0; ki < 2; ki++) {
                int r = (wq << 4) + (lane & 15);
                int u = ((2 * kg + ki) << 1) + (lane >> 4);
                uint32_t o = r * 256 + ((u ^ (r & 7)) << 4);
                uint32_t ah[4], al[4];
                ldsm4(ah, su + QH + o);
                ldsm4(al, su + QL + o);
#pragma unroll
                for (int n = 0; n < 8; n++) {
                    mma16816(sacc[n], ah, bk[n][2*ki], bk[n][2*ki+1]);
                    mma16816(sacc[n], al, bk[n][2*ki], bk[n][2*ki+1]);
                }
            }
        }

        if (kt == qt) {
            int r0 = (wq << 4) + (lane >> 2), r1 = r0 + 8;
            int cb = 2 * (lane & 3);
#pragma unroll
            for (int n = 0; n < 8; n++) {
                int c0 = (n << 3) + cb, c1 = c0 + 1;
                if (c0 > r0) sacc[n][0] = -1e30f;
                if (c1 > r0) sacc[n][1] = -1e30f;
                if (c0 > r1) sacc[n][2] = -1e30f;
                if (c1 > r1) sacc[n][3] = -1e30f;
            }
        }

        float mx0 = -1e30f, mx1 = -1e30f;
#pragma unroll
        for (int n = 0; n < 8; n++) {
            mx0 = fmaxf(mx0, fmaxf(sacc[n][0], sacc[n][1]));
            mx1 = fmaxf(mx1, fmaxf(sacc[n][2], sacc[n][3]));
        }
        mx0 = fmaxf(mx0, __shfl_xor_sync(0xffffffffu, mx0, 1));
        mx0 = fmaxf(mx0, __shfl_xor_sync(0xffffffffu, mx0, 2));
        mx1 = fmaxf(mx1, __shfl_xor_sync(0xffffffffu, mx1, 1));
        mx1 = fmaxf(mx1, __shfl_xor_sync(0xffffffffu, mx1, 2));
        float mn0 = fmaxf(m0, mx0), mn1 = fmaxf(m1, mx1);
        float al0 = __expf(m0 - mn0), al1 = __expf(m1 - mn1);
        float s0 = 0.f, s1 = 0.f;
#pragma unroll
        for (int n = 0; n < 8; n++) {
            sacc[n][0] = __expf(sacc[n][0] - mn0);
            sacc[n][1] = __expf(sacc[n][1] - mn0);
            sacc[n][2] = __expf(sacc[n][2] - mn1);
            sacc[n][3] = __expf(sacc[n][3] - mn1);
            s0 += sacc[n][0] + sacc[n][1];
            s1 += sacc[n][2] + sacc[n][3];
        }
        s0 += __shfl_xor_sync(0xffffffffu, s0, 1);
        s0 += __shfl_xor_sync(0xffffffffu, s0, 2);
        s1 += __shfl_xor_sync(0xffffffffu, s1, 1);
        s1 += __shfl_xor_sync(0xffffffffu, s1, 2);
        l0 = l0 * al0 + s0; l1 = l1 * al1 + s1;
        m0 = mn0; m1 = mn1;
#pragma unroll
        for (int t = 0; t < 16; t++) {
            oacc[t][0] *= al0; oacc[t][1] *= al0;
            oacc[t][2] *= al1; oacc[t][3] *= al1;
        }

        // ---- O += P V
#pragma unroll
        for (int ks = 0; ks < 4; ks++) {
            uint32_t ph[4], pl[4];
            ph[0] = pack_hi2h(sacc[2*ks][0],   sacc[2*ks][1]);
            ph[1] = pack_hi2h(sacc[2*ks][2],   sacc[2*ks][3]);
            ph[2] = pack_hi2h(sacc[2*ks+1][0], sacc[2*ks+1][1]);
            ph[3] = pack_hi2h(sacc[2*ks+1][2], sacc[2*ks+1][3]);
            pl[0] = pack_lo2h(sacc[2*ks][0],   sacc[2*ks][1]);
            pl[1] = pack_lo2h(sacc[2*ks][2],   sacc[2*ks][3]);
            pl[2] = pack_lo2h(sacc[2*ks+1][0], sacc[2*ks+1][1]);
            pl[3] = pack_lo2h(sacc[2*ks+1][2], sacc[2*ks+1][3]);
#pragma unroll
            for (int dg = 0; dg < 8; dg++) {
                int r = (ks << 4) + (lane & 15);
                int u = (dg << 1) + (lane >> 4);
                uint32_t bv[4];
                ldsm4t(bv, VS + r * 256 + ((u ^ (r & 7)) << 4));
                mma16816(oacc[2*dg],   ph, bv[0], bv[1]);
                mma16816(oacc[2*dg+1], ph, bv[2], bv[3]);
                mma16816(oacc[2*dg],   pl, bv[0], bv[1]);
                mma16816(oacc[2*dg+1], pl, bv[2], bv[3]);
            }
        }
        __syncthreads();
    }

    // ---- epilogue: O/l -> single fp16
    float i0 = 1.f / l0, i1 = 1.f / l1;
    size_t grow0 = rowbase + qi0 + (wq << 4) + (lane >> 2);
    size_t grow1 = grow0 + 8;
    int cb = hoff + 2 * (lane & 3);
#pragma unroll
    for (int t = 0; t < 16; t++) {
        int col = cb + (t << 3);
        *(uint32_t*)(Od + grow0 * Dm + col) = pack_hi2h(oacc[t][0] * i0, oacc[t][1] * i0);
        *(uint32_t*)(Od + grow1 * Dm + col) = pack_hi2h(oacc[t][2] * i1, oacc[t][3] * i1);
    }
}

// ---------------- launch ------------------------------------------------------
extern "C" void kernel_launch(void* const* d_in, const int* in_sizes, int n_in,
                              void* d_out, int out_size)
{
    const float* x  = (const float*)d_in[0];
    const int*  pos = (const int*)d_in[1];
    const float* Wq = (const float*)d_in[2];
    const float* Wk = (const float*)d_in[3];
    const float* Wv = (const float*)d_in[4];
    const float* Wo = (const float*)d_in[5];
    float* out = (float*)d_out;

    __half *ahi, *alo, *w, *qhi, *qlo, *kd, *vd;
    cudaGetSymbolAddress((void**)&ahi, g_ahi);
    cudaGetSymbolAddress((void**)&alo, g_alo);
    cudaGetSymbolAddress((void**)&w,   g_w);
    cudaGetSymbolAddress((void**)&qhi, g_qhi);
    cudaGetSymbolAddress((void**)&qlo, g_qlo);
    cudaGetSymbolAddress((void**)&kd,  g_k);
    cudaGetSymbolAddress((void**)&vd,  g_v);

    invf_kernel<<<1, 64>>>();

    const int nx4 = (Mm * Dm) / 4;
    const int nw4 = (Dm * Dm) / 4;

    cudaFuncSetAttribute(gemm_qkv,
                         cudaFuncAttributeMaxDynamicSharedMemorySize, GEMM_SMEM);
    cudaFuncSetAttribute(gemm_out,
                         cudaFuncAttributeMaxDynamicSharedMemorySize, G1_SMEM);
    cudaFuncSetAttribute(attn_mma,
                         cudaFuncAttributeMaxDynamicSharedMemorySize, ATT_SMEM);

    // x -> fp16 hi/lo
    split_x<<<nx4/256, 256>>>((const float4*)x, (__half2*)ahi, (__half2*)alo, nx4);
    // all 4 weights -> packed single fp16
    split4_w<<<(4*nw4)/256, 256>>>((const float4*)Wq, (const float4*)Wk,
                                   (const float4*)Wv, (const float4*)Wo, (__half2*)w);

    // fused QKV GEMM + RoPE + split (one launch, 3072 CTAs, 256 thr, 2 CTA/SM)
    dim3 qkvgrid(Dm/64, Mm/128, 3);
    gemm_qkv<<<qkvgrid, 256, GEMM_SMEM>>>(ahi, alo, w, pos, qhi, qlo, kd, vd);

    // attention -> O single fp16 into g_ahi
    dim3 agrid(Ll/64, Hn, Bb);
    attn_mma<<<agrid, 128, ATT_SMEM>>>(qhi, qlo, kd, vd, ahi);

    // out = O Wo^T (fp32, single-pass)
    dim3 ggrid(Dm/64, Mm/128);
    gemm_out<<<ggrid, 256, G1_SMEM>>>(ahi, w + (size_t)3*Dm*Dm, out, Dm, Dm);
}

// round 15
// speedup vs baseline: 1.6626x; 1.2561x over previous
#include <cuda_runtime.h>
#include <cuda_fp16.h>
#include <math.h>
#include <stdint.h>

#define Dm 2048
#define Hn 16
#define Dh 128
#define Bb 2
#define Ll 2048
#define Mm (Bb*Ll)   /* 4096 rows */
#define SCALE_C 0.08838834764831845f   /* 1/sqrt(128) */

// ---------------- scratch (static device globals; no runtime allocation) ----
__device__ __half g_a[(size_t)Mm * Dm];    // x fp16, later O fp16
__device__ __half g_w[(size_t)4 * Dm * Dm]; // Wq,Wk,Wv,Wo single fp16
__device__ __half g_q[(size_t)Mm * Dm];    // Q single fp16 (post-rope, scaled)
__device__ __half g_k[(size_t)Mm * Dm];    // K single fp16 (post-rope)
__device__ __half g_v[(size_t)Mm * Dm];    // V single fp16
__device__ float g_invf[Dh/2];

// ======================= helpers =============================================
__device__ __forceinline__ uint32_t smem_u32(const void* p) {
    uint32_t a;
    asm("{ .reg .u64 t; cvta.to.shared.u64 t, %1; cvt.u32.u64 %0, t; }"
        : "=r"(a) : "l"(p));
    return a;
}
__device__ __forceinline__ void cp_async16(uint32_t saddr, const void* gaddr) {
    asm volatile("cp.async.cg.shared.global [%0], [%1], 16;"
                 :: "r"(saddr), "l"(gaddr) : "memory");
}
#define CP_COMMIT() asm volatile("cp.async.commit_group;" ::: "memory")
#define CP_WAIT1()  asm volatile("cp.async.wait_group 1;" ::: "memory")
#define CP_WAIT0()  asm volatile("cp.async.wait_group 0;" ::: "memory")

__device__ __forceinline__ void ldsm4(uint32_t* d, uint32_t a) {
    asm volatile("ldmatrix.sync.aligned.m8n8.x4.shared.b16 {%0,%1,%2,%3}, [%4];"
                 : "=r"(d[0]), "=r"(d[1]), "=r"(d[2]), "=r"(d[3]) : "r"(a));
}
__device__ __forceinline__ void ldsm4t(uint32_t* d, uint32_t a) {
    asm volatile("ldmatrix.sync.aligned.m8n8.x4.trans.shared.b16 {%0,%1,%2,%3}, [%4];"
                 : "=r"(d[0]), "=r"(d[1]), "=r"(d[2]), "=r"(d[3]) : "r"(a));
}
__device__ __forceinline__ void mma16816(float* d, const uint32_t* a,
                                         uint32_t b0, uint32_t b1) {
    asm volatile(
        "mma.sync.aligned.m16n8k16.row.col.f32.f16.f16.f32 "
        "{%0,%1,%2,%3}, {%4,%5,%6,%7}, {%8,%9}, {%0,%1,%2,%3};"
        : "+f"(d[0]), "+f"(d[1]), "+f"(d[2]), "+f"(d[3])
        : "r"(a[0]), "r"(a[1]), "r"(a[2]), "r"(a[3]), "r"(b0), "r"(b1));
}
__device__ __forceinline__ uint32_t pack_hi2h(float a, float b) {
    __half2 t = __floats2half2_rn(a, b);
    return *reinterpret_cast<uint32_t*>(&t);
}

// ---------------- inv_freq table --------------------------------------------
__global__ void invf_kernel() {
    int i = threadIdx.x;
    if (i < Dh/2)
        g_invf[i] = (float)pow(10000.0, -(double)(2*i) / (double)Dh);
}

// ---------------- fp32 -> fp16 convert (x) ------------------------------------
__global__ void conv_x(const float4* __restrict__ src, __half2* __restrict__ dst, int n4)
{
    int i = blockIdx.x * blockDim.x + threadIdx.x;
    if (i >= n4) return;
    float4 v = src[i];
    dst[2*i]   = __floats2half2_rn(v.x, v.y);
    dst[2*i+1] = __floats2half2_rn(v.z, v.w);
}

// ---------------- all 4 weights -> packed single fp16 ------------------------
__global__ void split4_w(const float4* __restrict__ w0, const float4* __restrict__ w1,
                         const float4* __restrict__ w2, const float4* __restrict__ w3,
                         __half2* __restrict__ w)
{
    const int n4each = (Dm * Dm) / 4;     // 2^20
    int idx = blockIdx.x * blockDim.x + threadIdx.x;
    int t = idx >> 20;
    int r = idx & (n4each - 1);
    const float4* s = (t == 0) ? w0 : (t == 1) ? w1 : (t == 2) ? w2 : w3;
    float4 v = s[r];
    w[2*(size_t)idx]   = __floats2half2_rn(v.x, v.y);
    w[2*(size_t)idx+1] = __floats2half2_rn(v.z, v.w);
}

// ==== GEMM tiles: CTA 128x64, 256 thr, 8 warps (4x2 of 32x32), 2 stages ======
#define KC 64
#define TILE_A 16384
#define TILE_W 8192
#define G1_STAGE (TILE_A + TILE_W)      /* A+W = 24KB */
#define G1_SMEM (1024 + 2*G1_STAGE)

#define ISSUE1(cc) do {                                                        \
    uint32_t sbase = su + ((cc) & 1) * G1_STAGE;                               \
    const size_t kb = (size_t)(cc) * (KC * 2);                                 \
    {                                                                          \
        const char* g = srcA + kb;                                             \
        _Pragma("unroll")                                                      \
        for (int i = 0; i < 4; i++) {                                          \
            int u = tid + (i << 8);                                            \
            int r = u >> 3;                                                    \
            int cb = (u & 7) << 4;                                             \
            uint32_t off = ((r >> 3) << 10) + ((r & 7) << 7) + (cb ^ ((r & 7) << 4)); \
            cp_async16(sbase + off, g + (size_t)r * rstride + cb);             \
        }                                                                      \
    }                                                                          \
    {                                                                          \
        const char* g = srcW + kb;                                             \
        uint32_t s = sbase + TILE_A;                                           \
        _Pragma("unroll")                                                      \
        for (int i = 0; i < 2; i++) {                                          \
            int u = tid + (i << 8);                                            \
            int r = u >> 3;                                                    \
            int cb = (u & 7) << 4;                                             \
            uint32_t off = ((r >> 3) << 10) + ((r & 7) << 7) + (cb ^ ((r & 7) << 4)); \
            cp_async16(s + off, g + (size_t)r * rstride + cb);                 \
        }                                                                      \
    }                                                                          \
    CP_COMMIT();                                                               \
} while (0)

#define GEMM_MAINLOOP1()                                                       \
    uint32_t aoff[2], ar7[2];                                                  \
    _Pragma("unroll")                                                          \
    for (int m = 0; m < 2; m++) {                                              \
        int r = wm*32 + m*16 + (lane & 15);                                    \
        aoff[m] = ((r >> 3) << 10) + ((r & 7) << 7);                           \
        ar7[m]  = r & 7;                                                       \
    }                                                                          \
    uint32_t boff[4], br7[4];                                                  \
    _Pragma("unroll")                                                          \
    for (int n = 0; n < 4; n++) {                                              \
        int r = wn*32 + n*8 + (lane & 7);                                      \
        boff[n] = ((r >> 3) << 10) + ((r & 7) << 7);                           \
        br7[n]  = r & 7;                                                       \
    }                                                                          \
    const uint32_t uA_lo = lane >> 4;                                          \
    const uint32_t uB_lo = lane >> 3;                                          \
    float acc[2][4][4];                                                        \
    _Pragma("unroll")                                                          \
    for (int m = 0; m < 2; m++)                                                \
        _Pragma("unroll")                                                      \
        for (int n = 0; n < 4; n++)                                            \
            _Pragma("unroll")                                                  \
            for (int q = 0; q < 4; q++) acc[m][n][q] = 0.f;                    \
    const int NCH = Ko / KC;                                                   \
    ISSUE1(0);                                                                 \
    for (int c = 0; c < NCH; c++) {                                            \
        if (c + 1 < NCH) { ISSUE1(c + 1); CP_WAIT1(); }                        \
        else { CP_WAIT0(); }                                                   \
        __syncthreads();                                                       \
        const uint32_t st = su + (c & 1) * G1_STAGE;                           \
        const uint32_t SA = st;                                                \
        const uint32_t SB = st + TILE_A;                                       \
        _Pragma("unroll")                                                      \
        for (int kp = 0; kp < 2; kp++) {                                       \
            uint32_t bb[4][4];                                                 \
            _Pragma("unroll")                                                  \
            for (int n = 0; n < 4; n++) {                                      \
                uint32_t uB = 4*kp + uB_lo;                                    \
                ldsm4(bb[n], SB + boff[n] + ((uB ^ br7[n]) << 4));             \
            }                                                                  \
            _Pragma("unroll")                                                  \
            for (int ki = 0; ki < 2; ki++) {                                   \
                uint32_t uA = 2*(2*kp + ki) + uA_lo;                           \
                uint32_t ah[2][4];                                             \
                _Pragma("unroll")                                              \
                for (int m = 0; m < 2; m++)                                    \
                    ldsm4(ah[m], SA + aoff[m] + ((uA ^ ar7[m]) << 4));         \
                _Pragma("unroll")                                              \
                for (int m = 0; m < 2; m++)                                    \
                    _Pragma("unroll")                                          \
                    for (int n = 0; n < 4; n++)                                \
                        mma16816(acc[m][n], ah[m], bb[n][2*ki], bb[n][2*ki+1]); \
            }                                                                  \
        }                                                                      \
        __syncthreads();                                                       \
    }

// ---------------- fused QKV GEMM + RoPE + fp16 epilogue ----------------------
// grid (32, 32, 3): z=0 Q (rope+scale), z=1 K (rope), z=2 V. All single-pass.
__global__ void __launch_bounds__(256, 2)
gemm_qkv(const __half* __restrict__ Ax, const __half* __restrict__ W_all,
         const int* __restrict__ pos,
         __half* __restrict__ Qd, __half* __restrict__ Kd, __half* __restrict__ Vd)
{
    extern __shared__ char smraw[];
    char* smal = (char*)(((uintptr_t)smraw + 1023) & ~(uintptr_t)1023);
    const uint32_t su = smem_u32(smal);

    const int tid = threadIdx.x;
    const int lane = tid & 31, wid = tid >> 5;
    const int row0 = blockIdx.y << 7;       // 128 rows per CTA
    const int col0 = blockIdx.x << 6;       // 64 cols per CTA
    const int z = blockIdx.z;
    const int wm = wid >> 1, wn = wid & 1;  // 4x2 warp grid, warp tile 32x32
    const int Ko = Dm;
    const size_t rstride = (size_t)Ko * 2;

    const char* srcA = (const char*)(Ax + (size_t)row0 * Ko);
    const char* srcW = (const char*)(W_all + (size_t)z * Dm * Dm + (size_t)col0 * Ko);

    GEMM_MAINLOOP1();

    if (z == 2) {
        // V: single fp16
#pragma unroll
        for (int m = 0; m < 2; m++) {
            int rw = row0 + wm*32 + m*16 + (lane >> 2);
#pragma unroll
            for (int n = 0; n < 4; n++) {
                int cw = col0 + wn*32 + n*8 + ((lane & 3) << 1);
                *(uint32_t*)(Vd + (size_t)rw * Dm + cw)     = pack_hi2h(acc[m][n][0], acc[m][n][1]);
                *(uint32_t*)(Vd + (size_t)(rw+8) * Dm + cw) = pack_hi2h(acc[m][n][2], acc[m][n][3]);
            }
        }
    } else {
        // Q/K: RoPE (+ scale for Q), single fp16 out
        __half* Dd = (z == 0) ? Qd : Kd;
        const float scl = (z == 0) ? SCALE_C : 1.0f;
#pragma unroll
        for (int m = 0; m < 2; m++) {
            int rw = row0 + wm*32 + m*16 + (lane >> 2);
            float p0 = (float)pos[rw];
            float p1 = (float)pos[rw + 8];
#pragma unroll
            for (int n = 0; n < 4; n++) {
                int cw = col0 + wn*32 + n*8 + ((lane & 3) << 1);
                float inv = g_invf[(cw & 127) >> 1];
                float s0, c0, s1, c1;
                sincosf(p0 * inv, &s0, &c0);
                sincosf(p1 * inv, &s1, &c1);
                float e = acc[m][n][0], o = acc[m][n][1];
                *(uint32_t*)(Dd + (size_t)rw * Dm + cw) =
                    pack_hi2h((e*c0 - o*s0) * scl, (e*s0 + o*c0) * scl);
                e = acc[m][n][2]; o = acc[m][n][3];
                *(uint32_t*)(Dd + (size_t)(rw+8) * Dm + cw) =
                    pack_hi2h((e*c1 - o*s1) * scl, (e*s1 + o*c1) * scl);
            }
        }
    }
}

// -------- single-pass fp16 GEMM (fp32 out) for the Wo projection -------------
__global__ void __launch_bounds__(256, 2)
gemm_out(const __half* __restrict__ Ao, const __half* __restrict__ Bw,
         float* __restrict__ C, int Ko, int No)
{
    extern __shared__ char smraw[];
    char* smal = (char*)(((uintptr_t)smraw + 1023) & ~(uintptr_t)1023);
    const uint32_t su = smem_u32(smal);

    const int tid = threadIdx.x;
    const int lane = tid & 31, wid = tid >> 5;
    const int row0 = blockIdx.y << 7;
    const int col0 = blockIdx.x << 6;
    const int wm = wid >> 1, wn = wid & 1;

    const char* srcA = (const char*)(Ao + (size_t)row0 * Ko);
    const char* srcW = (const char*)(Bw + (size_t)col0 * Ko);
    const size_t rstride = (size_t)Ko * 2;

    GEMM_MAINLOOP1();

#pragma unroll
    for (int m = 0; m < 2; m++) {
        int rw = row0 + wm*32 + m*16 + (lane >> 2);
#pragma unroll
        for (int n = 0; n < 4; n++) {
            int cw = col0 + wn*32 + n*8 + ((lane & 3) << 1);
            *(float2*)(C + (size_t)rw * No + cw) =
                make_float2(acc[m][n][0], acc[m][n][1]);
            *(float2*)(C + (size_t)(rw + 8) * No + cw) =
                make_float2(acc[m][n][2], acc[m][n][3]);
        }
    }
}

// ---------------- tensor-core causal flash attention (single fp16) -----------
// SMEM: Q (16KB) + K/V double-buffered (2 x 32KB) = 80KB, occ 2
#define ATT_SMEM 81920

#define ATT_ISSUE(kt) do {                                                     \
    const int kj0 = (kt) << 6;                                                 \
    uint32_t sb = su + 16384 + ((kt) & 1) * 32768;                             \
    _Pragma("unroll")                                                          \
    for (int i = 0; i < 8; i++) {                                              \
        int u = tid + (i << 7);                                                \
        int r = u >> 4, cu = u & 15;                                           \
        uint32_t so = r * 256 + ((cu ^ (r & 7)) << 4);                         \
        size_t go = (rowbase + kj0 + r) * Dm + hoff + cu * 8;                  \
        cp_async16(sb + so, K_g + go);                                         \
        cp_async16(sb + 16384 + so, V_g + go);                                 \
    }                                                                          \
    CP_COMMIT();                                                               \
} while (0)

__global__ void __launch_bounds__(128, 2)
attn_mma(const __half* __restrict__ Q_g, const __half* __restrict__ K_g,
         const __half* __restrict__ V_g, __half* __restrict__ Od)
{
    extern __shared__ char sm[];
    const uint32_t su = smem_u32(sm);
    const uint32_t QS = 0;

    const int tid = threadIdx.x, lane = tid & 31, wq = tid >> 5;
    const int qt = (int)(gridDim.x - 1 - blockIdx.x);
    const int h = blockIdx.y, b = blockIdx.z;
    const int qi0 = qt << 6;
    const size_t rowbase = (size_t)b * Ll;
    const int hoff = h * Dh;

    ATT_ISSUE(0);

#pragma unroll
    for (int i = 0; i < 8; i++) {
        int idx = tid + (i << 7);
        int r = idx >> 4, u = idx & 15;
        uint32_t so = r * 256 + ((u ^ (r & 7)) << 4);
        *(float4*)(sm + QS + so) =
            *(const float4*)(Q_g + (rowbase + qi0 + r) * Dm + hoff + u * 8);
    }

    float oacc[16][4];
#pragma unroll
    for (int t = 0; t < 16; t++)
#pragma unroll
        for (int q = 0; q < 4; q++) oacc[t][q] = 0.f;
    float m0 = -1e30f, m1 = -1e30f, l0 = 0.f, l1 = 0.f;

    for (int kt = 0; kt <= qt; kt++) {
        if (kt < qt) { ATT_ISSUE(kt + 1); CP_WAIT1(); }
        else { CP_WAIT0(); }
        __syncthreads();
        const uint32_t KS = su + 16384 + (kt & 1) * 32768;
        const uint32_t VS = KS + 16384;

        // ---- S = Q K^T (single fp16)
        float sacc[8][4];
#pragma unroll
        for (int n = 0; n < 8; n++)
#pragma unroll
            for (int q = 0; q < 4; q++) sacc[n][q] = 0.f;

#pragma unroll
        for (int kg = 0; kg < 4; kg++) {
            uint32_t bk[8][4];
#pragma unroll
            for (int n = 0; n < 8; n++) {
                int r = (n << 3) + (lane & 7);
                int u = (kg << 2) + (lane >> 3);
                ldsm4(bk[n], KS + r * 256 + ((u ^ (r & 7)) << 4));
            }
#pragma unroll
            for (int ki = 0; ki < 2; ki++) {
                int r = (wq << 4) + (lane & 15);
                int u = ((2 * kg + ki) << 1) + (lane >> 4);
                uint32_t ah[4];
                ldsm4(ah, su + QS + r * 256 + ((u ^ (r & 7)) << 4));
#pragma unroll
                for (int n = 0; n < 8; n++)
                    mma16816(sacc[n], ah, bk[n][2*ki], bk[n][2*ki+1]);
            }
        }

        if (kt == qt) {
            int r0 = (wq << 4) + (lane >> 2), r1 = r0 + 8;
            int cb = 2 * (lane & 3);
#pragma unroll
            for (int n = 0; n < 8; n++) {
                int c0 = (n << 3) + cb, c1 = c0 + 1;
                if (c0 > r0) sacc[n][0] = -1e30f;
                if (c1 > r0) sacc[n][1] = -1e30f;
                if (c0 > r1) sacc[n][2] = -1e30f;
                if (c1 > r1) sacc[n][3] = -1e30f;
            }
        }

        float mx0 = -1e30f, mx1 = -1e30f;
#pragma unroll
        for (int n = 0; n < 8; n++) {
            mx0 = fmaxf(mx0, fmaxf(sacc[n][0], sacc[n][1]));
            mx1 = fmaxf(mx1, fmaxf(sacc[n][2], sacc[n][3]));
        }
        mx0 = fmaxf(mx0, __shfl_xor_sync(0xffffffffu, mx0, 1));
        mx0 = fmaxf(mx0, __shfl_xor_sync(0xffffffffu, mx0, 2));
        mx1 = fmaxf(mx1, __shfl_xor_sync(0xffffffffu, mx1, 1));
        mx1 = fmaxf(mx1, __shfl_xor_sync(0xffffffffu, mx1, 2));
        float mn0 = fmaxf(m0, mx0), mn1 = fmaxf(m1, mx1);
        float al0 = __expf(m0 - mn0), al1 = __expf(m1 - mn1);
        float s0 = 0.f, s1 = 0.f;
#pragma unroll
        for (int n = 0; n < 8; n++) {
            sacc[n][0] = __expf(sacc[n][0] - mn0);
            sacc[n][1] = __expf(sacc[n][1] - mn0);
            sacc[n][2] = __expf(sacc[n][2] - mn1);
            sacc[n][3] = __expf(sacc[n][3] - mn1);
            s0 += sacc[n][0] + sacc[n][1];
            s1 += sacc[n][2] + sacc[n][3];
        }
        s0 += __shfl_xor_sync(0xffffffffu, s0, 1);
        s0 += __shfl_xor_sync(0xffffffffu, s0, 2);
        s1 += __shfl_xor_sync(0xffffffffu, s1, 1);
        s1 += __shfl_xor_sync(0xffffffffu, s1, 2);
        l0 = l0 * al0 + s0; l1 = l1 * al1 + s1;
        m0 = mn0; m1 = mn1;
#pragma unroll
        for (int t = 0; t < 16; t++) {
            oacc[t][0] *= al0; oacc[t][1] *= al0;
            oacc[t][2] *= al1; oacc[t][3] *= al1;
        }

        // ---- O += P V (P single fp16)
#pragma unroll
        for (int ks = 0; ks < 4; ks++) {
            uint32_t ph[4];
            ph[0] = pack_hi2h(sacc[2*ks][0],   sacc[2*ks][1]);
            ph[1] = pack_hi2h(sacc[2*ks][2],   sacc[2*ks][3]);
            ph[2] = pack_hi2h(sacc[2*ks+1][0], sacc[2*ks+1][1]);
            ph[3] = pack_hi2h(sacc[2*ks+1][2], sacc[2*ks+1][3]);
#pragma unroll
            for (int dg = 0; dg < 8; dg++) {
                int r = (ks << 4) + (lane & 15);
                int u = (dg << 1) + (lane >> 4);
                uint32_t bv[4];
                ldsm4t(bv, VS + r * 256 + ((u ^ (r & 7)) << 4));
                mma16816(oacc[2*dg],   ph, bv[0], bv[1]);
                mma16816(oacc[2*dg+1], ph, bv[2], bv[3]);
            }
        }
        __syncthreads();
    }

    // ---- epilogue: O/l -> single fp16
    float i0 = 1.f / l0, i1 = 1.f / l1;
    size_t grow0 = rowbase + qi0 + (wq << 4) + (lane >> 2);
    size_t grow1 = grow0 + 8;
    int cb = hoff + 2 * (lane & 3);
#pragma unroll
    for (int t = 0; t < 16; t++) {
        int col = cb + (t << 3);
        *(uint32_t*)(Od + grow0 * Dm + col) = pack_hi2h(oacc[t][0] * i0, oacc[t][1] * i0);
        *(uint32_t*)(Od + grow1 * Dm + col) = pack_hi2h(oacc[t][2] * i1, oacc[t][3] * i1);
    }
}

// ---------------- launch ------------------------------------------------------
extern "C" void kernel_launch(void* const* d_in, const int* in_sizes, int n_in,
                              void* d_out, int out_size)
{
    const float* x  = (const float*)d_in[0];
    const int*  pos = (const int*)d_in[1];
    const float* Wq = (const float*)d_in[2];
    const float* Wk = (const float*)d_in[3];
    const float* Wv = (const float*)d_in[4];
    const float* Wo = (const float*)d_in[5];
    float* out = (float*)d_out;

    __half *ax, *w, *qd, *kd, *vd;
    cudaGetSymbolAddress((void**)&ax, g_a);
    cudaGetSymbolAddress((void**)&w,  g_w);
    cudaGetSymbolAddress((void**)&qd, g_q);
    cudaGetSymbolAddress((void**)&kd, g_k);
    cudaGetSymbolAddress((void**)&vd, g_v);

    invf_kernel<<<1, 64>>>();

    const int nx4 = (Mm * Dm) / 4;
    const int nw4 = (Dm * Dm) / 4;

    cudaFuncSetAttribute(gemm_qkv,
                         cudaFuncAttributeMaxDynamicSharedMemorySize, G1_SMEM);
    cudaFuncSetAttribute(gemm_out,
                         cudaFuncAttributeMaxDynamicSharedMemorySize, G1_SMEM);
    cudaFuncSetAttribute(attn_mma,
                         cudaFuncAttributeMaxDynamicSharedMemorySize, ATT_SMEM);

    // x -> fp16
    conv_x<<<nx4/256, 256>>>((const float4*)x, (__half2*)ax, nx4);
    // all 4 weights -> packed single fp16
    split4_w<<<(4*nw4)/256, 256>>>((const float4*)Wq, (const float4*)Wk,
                                   (const float4*)Wv, (const float4*)Wo, (__half2*)w);

    // fused QKV GEMM + RoPE (one launch, 3072 CTAs, 256 thr, 2 CTA/SM)
    dim3 qkvgrid(Dm/64, Mm/128, 3);
    gemm_qkv<<<qkvgrid, 256, G1_SMEM>>>(ax, w, pos, qd, kd, vd);

    // attention -> O single fp16 into g_a
    dim3 agrid(Ll/64, Hn, Bb);
    attn_mma<<<agrid, 128, ATT_SMEM>>>(qd, kd, vd, ax);

    // out = O Wo^T (fp32, single-pass)
    dim3 ggrid(Dm/64, Mm/128);
    gemm_out<<<ggrid, 256, G1_SMEM>>>(ax, w + (size_t)3*Dm*Dm, out, Dm, Dm);
}